// round 9
// baseline (speedup 1.0000x reference)
#include <cuda_runtime.h>
#include <math.h>
#include <stdint.h>

#define Bb 4
#define S 2048
#define D 512
#define H 4
#define HD 128
#define M_TOT (Bb*S)      // 8192
#define D2 (2*D)          // 1024
#define LN_EPS 1e-5f

// ------------------------------------------------------------------ scratch
__device__ float g_h[(size_t)M_TOT * D2];
__device__ float g_se_pre[(size_t)M_TOT * D];
__device__ float g_se[(size_t)M_TOT * D];
__device__ float g_qkv[3 * (size_t)M_TOT * D];    // q, k, v (all row-major [b*S+s][d])
__device__ float g_vt[(size_t)M_TOT * D];         // [B][D][S] (V^T per batch)
__device__ float g_ctx[(size_t)M_TOT * D];
__device__ float g_wet[1024 * 512];               // We^T [1024,512]
__device__ float g_wst[512 * 1024];               // Ws^T [512,1024]
__device__ float g_wqkv[3 * 512 * 512];           // Wq^T,Wk^T,Wv^T

// ------------------------------------------------------------------ utils
__device__ __forceinline__ uint32_t f2tf(float f) {
    uint32_t u; asm("cvt.rna.tf32.f32 %0, %1;" : "=r"(u) : "f"(f)); return u;
}

__device__ __forceinline__ void mma_tf32(float c[4], const uint32_t a[4], const uint32_t b[2]) {
    asm volatile(
        "mma.sync.aligned.m16n8k8.row.col.f32.tf32.tf32.f32 "
        "{%0,%1,%2,%3}, {%4,%5,%6,%7}, {%8,%9}, {%0,%1,%2,%3};"
        : "+f"(c[0]), "+f"(c[1]), "+f"(c[2]), "+f"(c[3])
        : "r"(a[0]), "r"(a[1]), "r"(a[2]), "r"(a[3]), "r"(b[0]), "r"(b[1]));
}

#define LDA 36    // padded smem leading dim (gemm, R4-proven)
#define FLDA 132  // padded smem leading dim (flash, R4-proven)

// ================================================================== GEMM path (R4 verbatim)
__device__ __forceinline__ void mma_mainloop(
    const float* __restrict__ Ap, long long lda,
    const float* __restrict__ Bp, long long ldb,
    int K, uint32_t (*As)[LDA], uint32_t (*Bs)[LDA], float acc[4][4][4])
{
    const int tid  = threadIdx.x;
    const int w    = tid >> 5, lane = tid & 31;
    const int gid  = lane >> 2, tig = lane & 3;
    const int wm   = w & 1, wn = w >> 1;

    const int srow = tid >> 3;
    const int sc4  = (tid & 7) * 4;

    float4 pa[4], pb[4];
#pragma unroll
    for (int i = 0; i < 4; i++) {
        pa[i] = *(const float4*)(Ap + (long long)(srow + i * 32) * lda + sc4);
        pb[i] = *(const float4*)(Bp + (long long)(srow + i * 32) * ldb + sc4);
    }

    const int nchunk = K >> 5;
    for (int c = 0; c < nchunk; c++) {
        __syncthreads();
#pragma unroll
        for (int i = 0; i < 4; i++) {
            const int r = srow + i * 32;
            As[r][sc4 + 0] = f2tf(pa[i].x); As[r][sc4 + 1] = f2tf(pa[i].y);
            As[r][sc4 + 2] = f2tf(pa[i].z); As[r][sc4 + 3] = f2tf(pa[i].w);
            Bs[r][sc4 + 0] = f2tf(pb[i].x); Bs[r][sc4 + 1] = f2tf(pb[i].y);
            Bs[r][sc4 + 2] = f2tf(pb[i].z); Bs[r][sc4 + 3] = f2tf(pb[i].w);
        }
        __syncthreads();

        if (c + 1 < nchunk) {
            const int k0 = (c + 1) << 5;
#pragma unroll
            for (int i = 0; i < 4; i++) {
                pa[i] = *(const float4*)(Ap + (long long)(srow + i * 32) * lda + k0 + sc4);
                pb[i] = *(const float4*)(Bp + (long long)(srow + i * 32) * ldb + k0 + sc4);
            }
        }

#pragma unroll
        for (int k8 = 0; k8 < 4; k8++) {
            const int kb = k8 * 8;
            uint32_t af[4][4], bf[4][2];
#pragma unroll
            for (int mt = 0; mt < 4; mt++) {
                const int r = wm * 64 + mt * 16 + gid;
                af[mt][0] = As[r][kb + tig];
                af[mt][1] = As[r + 8][kb + tig];
                af[mt][2] = As[r][kb + tig + 4];
                af[mt][3] = As[r + 8][kb + tig + 4];
            }
#pragma unroll
            for (int nt = 0; nt < 4; nt++) {
                const int n = wn * 32 + nt * 8 + gid;
                bf[nt][0] = Bs[n][kb + tig];
                bf[nt][1] = Bs[n][kb + tig + 4];
            }
#pragma unroll
            for (int mt = 0; mt < 4; mt++)
#pragma unroll
                for (int nt = 0; nt < 4; nt++)
                    mma_tf32(acc[mt][nt], af[mt], bf[nt]);
        }
    }
}

__global__ void __launch_bounds__(256)
mma_gemm(const float* __restrict__ A, long long lda, long long Azb, long long Azh,
         const float* __restrict__ Bt, long long ldb, long long Bzb, long long Bzh,
         float* __restrict__ C, long long ldc, long long Czb, long long Czh,
         const float* b0, const float* b1, const float* b2,
         const float* __restrict__ resid,
         int relu, int K, int zdiv)
{
    __shared__ uint32_t As[128][LDA];
    __shared__ uint32_t Bs[128][LDA];

    const int tid = threadIdx.x;
    const int z = blockIdx.z;
    const long long zb = z / zdiv, zh = z % zdiv;

    const float* Ap = A + zb * Azb + zh * Azh + (long long)blockIdx.y * 128 * lda;
    const float* Bp = Bt + zb * Bzb + zh * Bzh + (long long)blockIdx.x * 128 * ldb;

    float acc[4][4][4];
#pragma unroll
    for (int i = 0; i < 4; i++)
#pragma unroll
        for (int j = 0; j < 4; j++)
#pragma unroll
            for (int e = 0; e < 4; e++) acc[i][j][e] = 0.f;

    mma_mainloop(Ap, lda, Bp, ldb, K, As, Bs, acc);

    const float* bias = (z == 0) ? b0 : (z == 1) ? b1 : b2;
    const int w = tid >> 5, lane = tid & 31;
    const int gid = lane >> 2, tig = lane & 3;
    const int wm = w & 1, wn = w >> 1;
    float* Cz = C + zb * Czb + zh * Czh;

#pragma unroll
    for (int mt = 0; mt < 4; mt++) {
        const long long r0 = (long long)blockIdx.y * 128 + wm * 64 + mt * 16 + gid;
        const long long r1 = r0 + 8;
#pragma unroll
        for (int nt = 0; nt < 4; nt++) {
            const long long cb = (long long)blockIdx.x * 128 + wn * 32 + nt * 8 + tig * 2;
            float v0 = acc[mt][nt][0], v1 = acc[mt][nt][1];
            float v2 = acc[mt][nt][2], v3 = acc[mt][nt][3];
            if (bias) {
                const float bx = __ldg(bias + cb), by = __ldg(bias + cb + 1);
                v0 += bx; v1 += by; v2 += bx; v3 += by;
            }
            if (resid) {
                const float2 q0 = *(const float2*)(resid + r0 * ldc + cb);
                const float2 q1 = *(const float2*)(resid + r1 * ldc + cb);
                v0 += q0.x; v1 += q0.y; v2 += q1.x; v3 += q1.y;
            }
            if (relu) {
                v0 = fmaxf(v0, 0.f); v1 = fmaxf(v1, 0.f);
                v2 = fmaxf(v2, 0.f); v3 = fmaxf(v3, 0.f);
            }
            *(float2*)(Cz + r0 * ldc + cb) = make_float2(v0, v1);
            *(float2*)(Cz + r1 * ldc + cb) = make_float2(v2, v3);
        }
    }
}

// ================================================================== flash attention (R4 verbatim)
__global__ void __launch_bounds__(256)
flash_kernel(const float* __restrict__ qbase, const float* __restrict__ kbase,
             const float* __restrict__ pos, const float* __restrict__ alpha_p)
{
    extern __shared__ uint32_t sm[];
    uint32_t (*Qs)[FLDA] = (uint32_t(*)[FLDA])sm;
    uint32_t (*Ks)[FLDA] = (uint32_t(*)[FLDA])(sm + 128 * FLDA);
    uint32_t (*Vs)[FLDA] = (uint32_t(*)[FLDA])(sm + 2 * 128 * FLDA);
    float4* spos = (float4*)(sm + 3 * 128 * FLDA);

    const int tid  = threadIdx.x;
    const int w    = tid >> 5, lane = tid & 31;
    const int gid  = lane >> 2, tig = lane & 3;
    const int z    = blockIdx.y;
    const long long b = z / H, h = z % H;
    const int qt   = blockIdx.x;

    const float* Qp = qbase + b * ((long long)S * D) + h * HD + (long long)qt * 128 * D;
    const float* Kb = kbase + b * ((long long)S * D) + h * HD;
    const float* Vb = g_vt + b * ((long long)D * S) + (long long)h * HD * S;  // [hd][s]
    const float* pb = pos + b * ((long long)S * 3);

    // stage Q tile (tf32)
#pragma unroll
    for (int i = 0; i < 16; i++) {
        const int r = w + 8 * i;
        const float4 v = *(const float4*)(Qp + (long long)r * D + lane * 4);
        uint32_t* dst = &Qs[r][lane * 4];
        dst[0] = f2tf(v.x); dst[1] = f2tf(v.y); dst[2] = f2tf(v.z); dst[3] = f2tf(v.w);
    }

    const long long gr0 = (long long)qt * 128 + w * 16 + gid;
    const long long gr1 = gr0 + 8;
    const float px0 = __ldg(pb + gr0 * 3), py0 = __ldg(pb + gr0 * 3 + 1), pz0 = __ldg(pb + gr0 * 3 + 2);
    const float px1 = __ldg(pb + gr1 * 3), py1 = __ldg(pb + gr1 * 3 + 1), pz1 = __ldg(pb + gr1 * 3 + 2);
    const float sq0 = px0 * px0 + py0 * py0 + pz0 * pz0;
    const float sq1 = px1 * px1 + py1 * py1 + pz1 * pz1;

    float oacc[16][4];
#pragma unroll
    for (int i = 0; i < 16; i++)
#pragma unroll
        for (int e = 0; e < 4; e++) oacc[i][e] = 0.f;
    float m0 = -1e30f, m1 = -1e30f, l0 = 0.f, l1 = 0.f;

    const float scale = 0.08838834764831845f;  // 1/sqrt(128)
    const float alpha = __ldg(alpha_p);
    const int src0 = (lane & ~3) | (tig >> 1);
    const int src1 = src0 + 2;
    const bool odd = (tig & 1);

    for (int j = 0; j < 16; j++) {
        __syncthreads();
        const float* Kp = Kb + (long long)j * 128 * D;
#pragma unroll
        for (int i = 0; i < 16; i++) {
            const int r = w + 8 * i;
            const float4 v = *(const float4*)(Kp + (long long)r * D + lane * 4);
            uint32_t* dk = &Ks[r][lane * 4];
            dk[0] = f2tf(v.x); dk[1] = f2tf(v.y); dk[2] = f2tf(v.z); dk[3] = f2tf(v.w);
            const float4 u = *(const float4*)(Vb + (long long)r * S + j * 128 + lane * 4);
            uint32_t* dv = &Vs[r][lane * 4];
            dv[0] = f2tf(u.x); dv[1] = f2tf(u.y); dv[2] = f2tf(u.z); dv[3] = f2tf(u.w);
        }
        if (tid < 128) {
            const long long c = (long long)j * 128 + tid;
            const float x = pb[c * 3], y = pb[c * 3 + 1], zz = pb[c * 3 + 2];
            spos[tid] = make_float4(x, y, zz, x * x + y * y + zz * zz);
        }
        __syncthreads();

        // ---- S = Q @ K^T ----
        float sacc[16][4];
#pragma unroll
        for (int i = 0; i < 16; i++)
#pragma unroll
            for (int e = 0; e < 4; e++) sacc[i][e] = 0.f;

        const int ra = w * 16 + gid;
#pragma unroll
        for (int g = 0; g < 16; g++) {
            const int kb = g * 8;
            uint32_t af[4];
            af[0] = Qs[ra][kb + tig];
            af[1] = Qs[ra + 8][kb + tig];
            af[2] = Qs[ra][kb + tig + 4];
            af[3] = Qs[ra + 8][kb + tig + 4];
#pragma unroll
            for (int nt = 0; nt < 16; nt++) {
                uint32_t bf[2] = { Ks[nt * 8 + gid][kb + tig], Ks[nt * 8 + gid][kb + tig + 4] };
                mma_tf32(sacc[nt], af, bf);
            }
        }

        // ---- bias + online softmax ----
        float nm0 = m0, nm1 = m1;
#pragma unroll
        for (int nt = 0; nt < 16; nt++) {
            const int c0 = nt * 8 + tig * 2;
            const float4 q0 = spos[c0];
            const float4 q1 = spos[c0 + 1];
            float d;
            d = fmaxf(sq0 + q0.w - 2.f * (px0 * q0.x + py0 * q0.y + pz0 * q0.z), 0.f);
            sacc[nt][0] = sacc[nt][0] * scale - alpha * d;
            d = fmaxf(sq0 + q1.w - 2.f * (px0 * q1.x + py0 * q1.y + pz0 * q1.z), 0.f);
            sacc[nt][1] = sacc[nt][1] * scale - alpha * d;
            d = fmaxf(sq1 + q0.w - 2.f * (px1 * q0.x + py1 * q0.y + pz1 * q0.z), 0.f);
            sacc[nt][2] = sacc[nt][2] * scale - alpha * d;
            d = fmaxf(sq1 + q1.w - 2.f * (px1 * q1.x + py1 * q1.y + pz1 * q1.z), 0.f);
            sacc[nt][3] = sacc[nt][3] * scale - alpha * d;
            nm0 = fmaxf(nm0, fmaxf(sacc[nt][0], sacc[nt][1]));
            nm1 = fmaxf(nm1, fmaxf(sacc[nt][2], sacc[nt][3]));
        }
        nm0 = fmaxf(nm0, __shfl_xor_sync(0xffffffffu, nm0, 1));
        nm0 = fmaxf(nm0, __shfl_xor_sync(0xffffffffu, nm0, 2));
        nm1 = fmaxf(nm1, __shfl_xor_sync(0xffffffffu, nm1, 1));
        nm1 = fmaxf(nm1, __shfl_xor_sync(0xffffffffu, nm1, 2));

        const float f0 = __expf(m0 - nm0);
        const float f1 = __expf(m1 - nm1);
        m0 = nm0; m1 = nm1;

        float rs0 = 0.f, rs1 = 0.f;
#pragma unroll
        for (int nt = 0; nt < 16; nt++) {
            sacc[nt][0] = __expf(sacc[nt][0] - nm0);
            sacc[nt][1] = __expf(sacc[nt][1] - nm0);
            sacc[nt][2] = __expf(sacc[nt][2] - nm1);
            sacc[nt][3] = __expf(sacc[nt][3] - nm1);
            rs0 += sacc[nt][0] + sacc[nt][1];
            rs1 += sacc[nt][2] + sacc[nt][3];
        }
        rs0 += __shfl_xor_sync(0xffffffffu, rs0, 1);
        rs0 += __shfl_xor_sync(0xffffffffu, rs0, 2);
        rs1 += __shfl_xor_sync(0xffffffffu, rs1, 1);
        rs1 += __shfl_xor_sync(0xffffffffu, rs1, 2);
        l0 = l0 * f0 + rs0;
        l1 = l1 * f1 + rs1;

#pragma unroll
        for (int i = 0; i < 16; i++) {
            oacc[i][0] *= f0; oacc[i][1] *= f0;
            oacc[i][2] *= f1; oacc[i][3] *= f1;
        }

        // ---- O += P @ V ----
#pragma unroll
        for (int g = 0; g < 16; g++) {
            const float u00 = __shfl_sync(0xffffffffu, sacc[g][0], src0);
            const float u01 = __shfl_sync(0xffffffffu, sacc[g][1], src0);
            const float u10 = __shfl_sync(0xffffffffu, sacc[g][0], src1);
            const float u11 = __shfl_sync(0xffffffffu, sacc[g][1], src1);
            const float u20 = __shfl_sync(0xffffffffu, sacc[g][2], src0);
            const float u21 = __shfl_sync(0xffffffffu, sacc[g][3], src0);
            const float u30 = __shfl_sync(0xffffffffu, sacc[g][2], src1);
            const float u31 = __shfl_sync(0xffffffffu, sacc[g][3], src1);
            uint32_t af[4];
            af[0] = f2tf(odd ? u01 : u00);   // P[row0][tig]
            af[1] = f2tf(odd ? u21 : u20);   // P[row1][tig]
            af[2] = f2tf(odd ? u11 : u10);   // P[row0][tig+4]
            af[3] = f2tf(odd ? u31 : u30);   // P[row1][tig+4]
            const int kb = g * 8;
#pragma unroll
            for (int ng = 0; ng < 16; ng++) {
                uint32_t bf[2] = { Vs[ng * 8 + gid][kb + tig], Vs[ng * 8 + gid][kb + tig + 4] };
                mma_tf32(oacc[ng], af, bf);
            }
        }
    }

    // ---- epilogue: O / l -> ctx ----
    const float i0 = 1.f / l0, i1 = 1.f / l1;
    float* Cb = g_ctx + b * ((long long)S * D) + h * HD;
    const long long cr0 = (long long)qt * 128 + w * 16 + gid;
#pragma unroll
    for (int ng = 0; ng < 16; ng++) {
        const int col = ng * 8 + tig * 2;
        *(float2*)(Cb + cr0 * D + col)       = make_float2(oacc[ng][0] * i0, oacc[ng][1] * i0);
        *(float2*)(Cb + (cr0 + 8) * D + col) = make_float2(oacc[ng][2] * i1, oacc[ng][3] * i1);
    }
}

// ------------------------------------------------------------------ batched weight transpose
__global__ void transpose_all_kernel(const float* __restrict__ We, const float* __restrict__ Ws,
                                     const float* __restrict__ Wq, const float* __restrict__ Wk,
                                     const float* __restrict__ Wv,
                                     float* __restrict__ wet, float* __restrict__ wst,
                                     float* __restrict__ wqkv)
{
    __shared__ float t[32][33];
    const int z = blockIdx.z;
    const float* in; float* out; int R, C;
    switch (z) {
        case 0: in = We; out = wet;              R = D;  C = D2; break;
        case 1: in = Ws; out = wst;              R = D2; C = D;  break;
        case 2: in = Wq; out = wqkv + 0 * D * D; R = D;  C = D;  break;
        case 3: in = Wk; out = wqkv + 1 * D * D; R = D;  C = D;  break;
        default: in = Wv; out = wqkv + 2 * D * D; R = D; C = D;  break;
    }
    const int bx = blockIdx.x * 32, by = blockIdx.y * 32;
    if (bx >= C || by >= R) return;
    const int tx = threadIdx.x, ty = threadIdx.y;
#pragma unroll
    for (int dy = 0; dy < 32; dy += 8)
        t[ty + dy][tx] = in[(size_t)(by + ty + dy) * C + bx + tx];
    __syncthreads();
#pragma unroll
    for (int dy = 0; dy < 32; dy += 8)
        out[(size_t)(bx + ty + dy) * R + by + tx] = t[tx][ty + dy];
}

// ------------------------------------------------------------------ V transpose: [b][s][d] -> [b][d][s]
__global__ void vtrans_kernel(const float* __restrict__ v, float* __restrict__ vt)
{
    __shared__ float t[32][33];
    const int b = blockIdx.z;
    const int d0 = blockIdx.x * 32, s0 = blockIdx.y * 32;
    const int tx = threadIdx.x, ty = threadIdx.y;
    const float* in = v + (size_t)b * S * D;
    float* out = vt + (size_t)b * D * S;
#pragma unroll
    for (int dy = 0; dy < 32; dy += 8)
        t[ty + dy][tx] = in[(size_t)(s0 + ty + dy) * D + d0 + tx];
    __syncthreads();
#pragma unroll
    for (int dy = 0; dy < 32; dy += 8)
        out[(size_t)(d0 + ty + dy) * S + s0 + tx] = t[tx][ty + dy];
}

// ------------------------------------------------------------------ LayerNorm
__global__ void ln_kernel(const float* __restrict__ x, const float* __restrict__ x2,
                          const float* __restrict__ gamma, const float* __restrict__ beta,
                          float* __restrict__ out)
{
    __shared__ float red[128];
    const int row = blockIdx.x, t = threadIdx.x;
    const size_t base = (size_t)row * D + t * 4;

    float4 v = *(const float4*)(x + base);
    if (x2) {
        float4 w = *(const float4*)(x2 + base);
        v.x += w.x; v.y += w.y; v.z += w.z; v.w += w.w;
    }
    red[t] = v.x + v.y + v.z + v.w; __syncthreads();
    for (int s2 = 64; s2 > 0; s2 >>= 1) {
        if (t < s2) red[t] += red[t + s2];
        __syncthreads();
    }
    const float mean = red[0] * (1.f / D); __syncthreads();

    float dx = v.x - mean, dy = v.y - mean, dz = v.z - mean, dw = v.w - mean;
    red[t] = dx * dx + dy * dy + dz * dz + dw * dw; __syncthreads();
    for (int s2 = 64; s2 > 0; s2 >>= 1) {
        if (t < s2) red[t] += red[t + s2];
        __syncthreads();
    }
    const float inv = rsqrtf(red[0] * (1.f / D) + LN_EPS);

    float4 g = *(const float4*)(gamma + t * 4);
    float4 bt = *(const float4*)(beta + t * 4);
    float4 o;
    o.x = dx * inv * g.x + bt.x;
    o.y = dy * inv * g.y + bt.y;
    o.z = dz * inv * g.z + bt.z;
    o.w = dw * inv * g.w + bt.w;
    *(float4*)(out + base) = o;
}

// ------------------------------------------------------------------ host
extern "C" void kernel_launch(void* const* d_in, const int* in_sizes, int n_in,
                              void* d_out, int out_size)
{
    const float* input   = (const float*)d_in[0];
    const float* pos     = (const float*)d_in[1];
    const float* We      = (const float*)d_in[2];
    const float* be      = (const float*)d_in[3];
    const float* Ws      = (const float*)d_in[4];
    const float* bs      = (const float*)d_in[5];
    const float* gamma   = (const float*)d_in[6];
    const float* beta    = (const float*)d_in[7];
    const float* Wq      = (const float*)d_in[8];
    const float* bq      = (const float*)d_in[9];
    const float* Wk      = (const float*)d_in[10];
    const float* bk      = (const float*)d_in[11];
    const float* Wv      = (const float*)d_in[12];
    const float* bv      = (const float*)d_in[13];
    const float* alpha_p = (const float*)d_in[14];
    float* out = (float*)d_out;

    float *h, *se_pre, *se, *qkv, *vt, *ctx, *wet, *wst, *wqkv;
    cudaGetSymbolAddress((void**)&h,      g_h);
    cudaGetSymbolAddress((void**)&se_pre, g_se_pre);
    cudaGetSymbolAddress((void**)&se,     g_se);
    cudaGetSymbolAddress((void**)&qkv,    g_qkv);
    cudaGetSymbolAddress((void**)&vt,     g_vt);
    cudaGetSymbolAddress((void**)&ctx,    g_ctx);
    cudaGetSymbolAddress((void**)&wet,    g_wet);
    cudaGetSymbolAddress((void**)&wst,    g_wst);
    cudaGetSymbolAddress((void**)&wqkv,   g_wqkv);

    static bool attr_set = false;
    const int flash_smem = (3 * 128 * FLDA) * 4 + 128 * 16;   // 204800 B
    if (!attr_set) {
        cudaFuncSetAttribute(flash_kernel, cudaFuncAttributeMaxDynamicSharedMemorySize, flash_smem);
        attr_set = true;
    }

    // 0. all weight transposes in one launch
    transpose_all_kernel<<<dim3(32, 32, 5), dim3(32, 8)>>>(
        We, Ws, Wq, Wk, Wv, wet, wst, wqkv);

    // 1. h = relu(input @ We + be)
    mma_gemm<<<dim3(D2 / 128, M_TOT / 128, 1), 256>>>(
        input, D, 0, 0,  wet, D, 0, 0,  h, D2, 0, 0,
        be, be, be, nullptr, 1, D, 1);
    // 2. se_pre = input + h @ Ws + bs
    mma_gemm<<<dim3(D / 128, M_TOT / 128, 1), 256>>>(
        h, D2, 0, 0,  wst, D2, 0, 0,  se_pre, D, 0, 0,
        bs, bs, bs, input, 0, D2, 1);
    // 3. se = LN(se_pre)
    ln_kernel<<<M_TOT, 128>>>(se_pre, nullptr, gamma, beta, se);
    // 4. q/k/v (z=0,1,2), all coalesced row-major
    mma_gemm<<<dim3(D / 128, M_TOT / 128, 3), 256>>>(
        se, D, 0, 0,
        wqkv, D, (long long)D * D, 0,
        qkv, D, (long long)M_TOT * D, 0,
        bq, bk, bv, nullptr, 0, D, 1);
    // 4b. vt[b][d][s] = v[b][s][d] (coalesced tiled transpose)
    vtrans_kernel<<<dim3(D / 32, S / 32, Bb), dim3(32, 8)>>>(
        qkv + 2 * (size_t)M_TOT * D, vt);
    // 5-7. fused flash attention -> ctx
    flash_kernel<<<dim3(S / 128, Bb * H), 256, flash_smem>>>(
        qkv, qkv + (size_t)M_TOT * D, pos, alpha_p);
    // 8. out = LN(se + ctx)
    ln_kernel<<<M_TOT, 128>>>(se, ctx, gamma, beta, out);
}

// round 10
// speedup vs baseline: 1.0361x; 1.0361x over previous
#include <cuda_runtime.h>
#include <math.h>
#include <stdint.h>

#define Bb 4
#define S 2048
#define D 512
#define H 4
#define HD 128
#define M_TOT (Bb*S)      // 8192
#define D2 (2*D)          // 1024
#define LN_EPS 1e-5f

// ------------------------------------------------------------------ scratch
__device__ float g_h[(size_t)M_TOT * D2];
__device__ float g_se_pre[(size_t)M_TOT * D];
__device__ float g_se[(size_t)M_TOT * D];
__device__ float g_qk[2 * (size_t)M_TOT * D];     // q then k
__device__ float g_vt[(size_t)M_TOT * D];         // [B][D][S] (V^T per batch)
__device__ float g_ctx[(size_t)M_TOT * D];
__device__ float g_wet[1024 * 512];               // We^T [1024,512]
__device__ float g_wst[512 * 1024];               // Ws^T [512,1024]
__device__ float g_wqkv[3 * 512 * 512];           // Wq^T,Wk^T,Wv^T

// ------------------------------------------------------------------ utils
__device__ __forceinline__ uint32_t f2tf(float f) {
    uint32_t u; asm("cvt.rna.tf32.f32 %0, %1;" : "=r"(u) : "f"(f)); return u;
}

__device__ __forceinline__ void mma_tf32(float c[4], const uint32_t a[4], const uint32_t b[2]) {
    asm volatile(
        "mma.sync.aligned.m16n8k8.row.col.f32.tf32.tf32.f32 "
        "{%0,%1,%2,%3}, {%4,%5,%6,%7}, {%8,%9}, {%0,%1,%2,%3};"
        : "+f"(c[0]), "+f"(c[1]), "+f"(c[2]), "+f"(c[3])
        : "r"(a[0]), "r"(a[1]), "r"(a[2]), "r"(a[3]), "r"(b[0]), "r"(b[1]));
}

#define LDA 36    // padded smem leading dim (gemm, R4-proven: 36KB static -> 2 CTAs/SM)
#define FLDA 132  // padded smem leading dim (flash, R4-proven)

// ================================================================== GEMM path (R4 verbatim)
__device__ __forceinline__ void mma_mainloop(
    const float* __restrict__ Ap, long long lda,
    const float* __restrict__ Bp, long long ldb,
    int K, uint32_t (*As)[LDA], uint32_t (*Bs)[LDA], float acc[4][4][4])
{
    const int tid  = threadIdx.x;
    const int w    = tid >> 5, lane = tid & 31;
    const int gid  = lane >> 2, tig = lane & 3;
    const int wm   = w & 1, wn = w >> 1;

    const int srow = tid >> 3;
    const int sc4  = (tid & 7) * 4;

    float4 pa[4], pb[4];
#pragma unroll
    for (int i = 0; i < 4; i++) {
        pa[i] = *(const float4*)(Ap + (long long)(srow + i * 32) * lda + sc4);
        pb[i] = *(const float4*)(Bp + (long long)(srow + i * 32) * ldb + sc4);
    }

    const int nchunk = K >> 5;
    for (int c = 0; c < nchunk; c++) {
        __syncthreads();
#pragma unroll
        for (int i = 0; i < 4; i++) {
            const int r = srow + i * 32;
            As[r][sc4 + 0] = f2tf(pa[i].x); As[r][sc4 + 1] = f2tf(pa[i].y);
            As[r][sc4 + 2] = f2tf(pa[i].z); As[r][sc4 + 3] = f2tf(pa[i].w);
            Bs[r][sc4 + 0] = f2tf(pb[i].x); Bs[r][sc4 + 1] = f2tf(pb[i].y);
            Bs[r][sc4 + 2] = f2tf(pb[i].z); Bs[r][sc4 + 3] = f2tf(pb[i].w);
        }
        __syncthreads();

        if (c + 1 < nchunk) {
            const int k0 = (c + 1) << 5;
#pragma unroll
            for (int i = 0; i < 4; i++) {
                pa[i] = *(const float4*)(Ap + (long long)(srow + i * 32) * lda + k0 + sc4);
                pb[i] = *(const float4*)(Bp + (long long)(srow + i * 32) * ldb + k0 + sc4);
            }
        }

#pragma unroll
        for (int k8 = 0; k8 < 4; k8++) {
            const int kb = k8 * 8;
            uint32_t af[4][4], bf[4][2];
#pragma unroll
            for (int mt = 0; mt < 4; mt++) {
                const int r = wm * 64 + mt * 16 + gid;
                af[mt][0] = As[r][kb + tig];
                af[mt][1] = As[r + 8][kb + tig];
                af[mt][2] = As[r][kb + tig + 4];
                af[mt][3] = As[r + 8][kb + tig + 4];
            }
#pragma unroll
            for (int nt = 0; nt < 4; nt++) {
                const int n = wn * 32 + nt * 8 + gid;
                bf[nt][0] = Bs[n][kb + tig];
                bf[nt][1] = Bs[n][kb + tig + 4];
            }
#pragma unroll
            for (int mt = 0; mt < 4; mt++)
#pragma unroll
                for (int nt = 0; nt < 4; nt++)
                    mma_tf32(acc[mt][nt], af[mt], bf[nt]);
        }
    }
}

__global__ void __launch_bounds__(256)
mma_gemm(const float* __restrict__ A, long long lda, long long Azb, long long Azh,
         const float* __restrict__ Bt, long long ldb, long long Bzb, long long Bzh,
         float* __restrict__ C, long long ldc, long long Czb, long long Czh,
         const float* b0, const float* b1, const float* b2,
         const float* __restrict__ resid, float* __restrict__ vt, int vt_z,
         int relu, int K, int zdiv)
{
    __shared__ uint32_t As[128][LDA];
    __shared__ uint32_t Bs[128][LDA];

    const int tid = threadIdx.x;
    const int z = blockIdx.z;
    const long long zb = z / zdiv, zh = z % zdiv;

    const float* Ap = A + zb * Azb + zh * Azh + (long long)blockIdx.y * 128 * lda;
    const float* Bp = Bt + zb * Bzb + zh * Bzh + (long long)blockIdx.x * 128 * ldb;

    float acc[4][4][4];
#pragma unroll
    for (int i = 0; i < 4; i++)
#pragma unroll
        for (int j = 0; j < 4; j++)
#pragma unroll
            for (int e = 0; e < 4; e++) acc[i][j][e] = 0.f;

    mma_mainloop(Ap, lda, Bp, ldb, K, As, Bs, acc);

    const float* bias = (z == 0) ? b0 : (z == 1) ? b1 : b2;
    const int w = tid >> 5, lane = tid & 31;
    const int gid = lane >> 2, tig = lane & 3;
    const int wm = w & 1, wn = w >> 1;
    float* Cz = C + zb * Czb + zh * Czh;
    const bool dotrans = (vt != nullptr) && (z == vt_z);

#pragma unroll
    for (int mt = 0; mt < 4; mt++) {
        const long long r0 = (long long)blockIdx.y * 128 + wm * 64 + mt * 16 + gid;
        const long long r1 = r0 + 8;
#pragma unroll
        for (int nt = 0; nt < 4; nt++) {
            const long long cb = (long long)blockIdx.x * 128 + wn * 32 + nt * 8 + tig * 2;
            float v0 = acc[mt][nt][0], v1 = acc[mt][nt][1];
            float v2 = acc[mt][nt][2], v3 = acc[mt][nt][3];
            if (bias) {
                const float bx = __ldg(bias + cb), by = __ldg(bias + cb + 1);
                v0 += bx; v1 += by; v2 += bx; v3 += by;
            }
            if (resid) {
                const float2 q0 = *(const float2*)(resid + r0 * ldc + cb);
                const float2 q1 = *(const float2*)(resid + r1 * ldc + cb);
                v0 += q0.x; v1 += q0.y; v2 += q1.x; v3 += q1.y;
            }
            if (relu) {
                v0 = fmaxf(v0, 0.f); v1 = fmaxf(v1, 0.f);
                v2 = fmaxf(v2, 0.f); v3 = fmaxf(v3, 0.f);
            }
            if (dotrans) {
                const long long b0r = r0 >> 11, s0 = r0 & (S - 1);
                const long long b1r = r1 >> 11, s1 = r1 & (S - 1);
                float* vb0 = vt + b0r * ((long long)D * S);
                float* vb1 = vt + b1r * ((long long)D * S);
                vb0[cb * S + s0] = v0; vb0[(cb + 1) * S + s0] = v1;
                vb1[cb * S + s1] = v2; vb1[(cb + 1) * S + s1] = v3;
            } else {
                *(float2*)(Cz + r0 * ldc + cb) = make_float2(v0, v1);
                *(float2*)(Cz + r1 * ldc + cb) = make_float2(v2, v3);
            }
        }
    }
}

// ================================================================== flash attention (R4 verbatim)
__global__ void __launch_bounds__(256)
flash_kernel(const float* __restrict__ qbase, const float* __restrict__ kbase,
             const float* __restrict__ pos, const float* __restrict__ alpha_p)
{
    extern __shared__ uint32_t sm[];
    uint32_t (*Qs)[FLDA] = (uint32_t(*)[FLDA])sm;
    uint32_t (*Ks)[FLDA] = (uint32_t(*)[FLDA])(sm + 128 * FLDA);
    uint32_t (*Vs)[FLDA] = (uint32_t(*)[FLDA])(sm + 2 * 128 * FLDA);
    float4* spos = (float4*)(sm + 3 * 128 * FLDA);

    const int tid  = threadIdx.x;
    const int w    = tid >> 5, lane = tid & 31;
    const int gid  = lane >> 2, tig = lane & 3;
    const int z    = blockIdx.y;
    const long long b = z / H, h = z % H;
    const int qt   = blockIdx.x;

    const float* Qp = qbase + b * ((long long)S * D) + h * HD + (long long)qt * 128 * D;
    const float* Kb = kbase + b * ((long long)S * D) + h * HD;
    const float* Vb = g_vt + b * ((long long)D * S) + (long long)h * HD * S;  // [hd][s]
    const float* pb = pos + b * ((long long)S * 3);

    // stage Q tile (tf32)
#pragma unroll
    for (int i = 0; i < 16; i++) {
        const int r = w + 8 * i;
        const float4 v = *(const float4*)(Qp + (long long)r * D + lane * 4);
        uint32_t* dst = &Qs[r][lane * 4];
        dst[0] = f2tf(v.x); dst[1] = f2tf(v.y); dst[2] = f2tf(v.z); dst[3] = f2tf(v.w);
    }

    const long long gr0 = (long long)qt * 128 + w * 16 + gid;
    const long long gr1 = gr0 + 8;
    const float px0 = __ldg(pb + gr0 * 3), py0 = __ldg(pb + gr0 * 3 + 1), pz0 = __ldg(pb + gr0 * 3 + 2);
    const float px1 = __ldg(pb + gr1 * 3), py1 = __ldg(pb + gr1 * 3 + 1), pz1 = __ldg(pb + gr1 * 3 + 2);
    const float sq0 = px0 * px0 + py0 * py0 + pz0 * pz0;
    const float sq1 = px1 * px1 + py1 * py1 + pz1 * pz1;

    float oacc[16][4];
#pragma unroll
    for (int i = 0; i < 16; i++)
#pragma unroll
        for (int e = 0; e < 4; e++) oacc[i][e] = 0.f;
    float m0 = -1e30f, m1 = -1e30f, l0 = 0.f, l1 = 0.f;

    const float scale = 0.08838834764831845f;  // 1/sqrt(128)
    const float alpha = __ldg(alpha_p);
    const int src0 = (lane & ~3) | (tig >> 1);
    const int src1 = src0 + 2;
    const bool odd = (tig & 1);

    for (int j = 0; j < 16; j++) {
        __syncthreads();
        const float* Kp = Kb + (long long)j * 128 * D;
#pragma unroll
        for (int i = 0; i < 16; i++) {
            const int r = w + 8 * i;
            const float4 v = *(const float4*)(Kp + (long long)r * D + lane * 4);
            uint32_t* dk = &Ks[r][lane * 4];
            dk[0] = f2tf(v.x); dk[1] = f2tf(v.y); dk[2] = f2tf(v.z); dk[3] = f2tf(v.w);
            const float4 u = *(const float4*)(Vb + (long long)r * S + j * 128 + lane * 4);
            uint32_t* dv = &Vs[r][lane * 4];
            dv[0] = f2tf(u.x); dv[1] = f2tf(u.y); dv[2] = f2tf(u.z); dv[3] = f2tf(u.w);
        }
        if (tid < 128) {
            const long long c = (long long)j * 128 + tid;
            const float x = pb[c * 3], y = pb[c * 3 + 1], zz = pb[c * 3 + 2];
            spos[tid] = make_float4(x, y, zz, x * x + y * y + zz * zz);
        }
        __syncthreads();

        // ---- S = Q @ K^T ----
        float sacc[16][4];
#pragma unroll
        for (int i = 0; i < 16; i++)
#pragma unroll
            for (int e = 0; e < 4; e++) sacc[i][e] = 0.f;

        const int ra = w * 16 + gid;
#pragma unroll
        for (int g = 0; g < 16; g++) {
            const int kb = g * 8;
            uint32_t af[4];
            af[0] = Qs[ra][kb + tig];
            af[1] = Qs[ra + 8][kb + tig];
            af[2] = Qs[ra][kb + tig + 4];
            af[3] = Qs[ra + 8][kb + tig + 4];
#pragma unroll
            for (int nt = 0; nt < 16; nt++) {
                uint32_t bf[2] = { Ks[nt * 8 + gid][kb + tig], Ks[nt * 8 + gid][kb + tig + 4] };
                mma_tf32(sacc[nt], af, bf);
            }
        }

        // ---- bias + online softmax ----
        float nm0 = m0, nm1 = m1;
#pragma unroll
        for (int nt = 0; nt < 16; nt++) {
            const int c0 = nt * 8 + tig * 2;
            const float4 q0 = spos[c0];
            const float4 q1 = spos[c0 + 1];
            float d;
            d = fmaxf(sq0 + q0.w - 2.f * (px0 * q0.x + py0 * q0.y + pz0 * q0.z), 0.f);
            sacc[nt][0] = sacc[nt][0] * scale - alpha * d;
            d = fmaxf(sq0 + q1.w - 2.f * (px0 * q1.x + py0 * q1.y + pz0 * q1.z), 0.f);
            sacc[nt][1] = sacc[nt][1] * scale - alpha * d;
            d = fmaxf(sq1 + q0.w - 2.f * (px1 * q0.x + py1 * q0.y + pz1 * q0.z), 0.f);
            sacc[nt][2] = sacc[nt][2] * scale - alpha * d;
            d = fmaxf(sq1 + q1.w - 2.f * (px1 * q1.x + py1 * q1.y + pz1 * q1.z), 0.f);
            sacc[nt][3] = sacc[nt][3] * scale - alpha * d;
            nm0 = fmaxf(nm0, fmaxf(sacc[nt][0], sacc[nt][1]));
            nm1 = fmaxf(nm1, fmaxf(sacc[nt][2], sacc[nt][3]));
        }
        nm0 = fmaxf(nm0, __shfl_xor_sync(0xffffffffu, nm0, 1));
        nm0 = fmaxf(nm0, __shfl_xor_sync(0xffffffffu, nm0, 2));
        nm1 = fmaxf(nm1, __shfl_xor_sync(0xffffffffu, nm1, 1));
        nm1 = fmaxf(nm1, __shfl_xor_sync(0xffffffffu, nm1, 2));

        const float f0 = __expf(m0 - nm0);
        const float f1 = __expf(m1 - nm1);
        m0 = nm0; m1 = nm1;

        float rs0 = 0.f, rs1 = 0.f;
#pragma unroll
        for (int nt = 0; nt < 16; nt++) {
            sacc[nt][0] = __expf(sacc[nt][0] - nm0);
            sacc[nt][1] = __expf(sacc[nt][1] - nm0);
            sacc[nt][2] = __expf(sacc[nt][2] - nm1);
            sacc[nt][3] = __expf(sacc[nt][3] - nm1);
            rs0 += sacc[nt][0] + sacc[nt][1];
            rs1 += sacc[nt][2] + sacc[nt][3];
        }
        rs0 += __shfl_xor_sync(0xffffffffu, rs0, 1);
        rs0 += __shfl_xor_sync(0xffffffffu, rs0, 2);
        rs1 += __shfl_xor_sync(0xffffffffu, rs1, 1);
        rs1 += __shfl_xor_sync(0xffffffffu, rs1, 2);
        l0 = l0 * f0 + rs0;
        l1 = l1 * f1 + rs1;

#pragma unroll
        for (int i = 0; i < 16; i++) {
            oacc[i][0] *= f0; oacc[i][1] *= f0;
            oacc[i][2] *= f1; oacc[i][3] *= f1;
        }

        // ---- O += P @ V ----
#pragma unroll
        for (int g = 0; g < 16; g++) {
            const float u00 = __shfl_sync(0xffffffffu, sacc[g][0], src0);
            const float u01 = __shfl_sync(0xffffffffu, sacc[g][1], src0);
            const float u10 = __shfl_sync(0xffffffffu, sacc[g][0], src1);
            const float u11 = __shfl_sync(0xffffffffu, sacc[g][1], src1);
            const float u20 = __shfl_sync(0xffffffffu, sacc[g][2], src0);
            const float u21 = __shfl_sync(0xffffffffu, sacc[g][3], src0);
            const float u30 = __shfl_sync(0xffffffffu, sacc[g][2], src1);
            const float u31 = __shfl_sync(0xffffffffu, sacc[g][3], src1);
            uint32_t af[4];
            af[0] = f2tf(odd ? u01 : u00);   // P[row0][tig]
            af[1] = f2tf(odd ? u21 : u20);   // P[row1][tig]
            af[2] = f2tf(odd ? u11 : u10);   // P[row0][tig+4]
            af[3] = f2tf(odd ? u31 : u30);   // P[row1][tig+4]
            const int kb = g * 8;
#pragma unroll
            for (int ng = 0; ng < 16; ng++) {
                uint32_t bf[2] = { Vs[ng * 8 + gid][kb + tig], Vs[ng * 8 + gid][kb + tig + 4] };
                mma_tf32(oacc[ng], af, bf);
            }
        }
    }

    // ---- epilogue: O / l -> ctx ----
    const float i0 = 1.f / l0, i1 = 1.f / l1;
    float* Cb = g_ctx + b * ((long long)S * D) + h * HD;
    const long long cr0 = (long long)qt * 128 + w * 16 + gid;
#pragma unroll
    for (int ng = 0; ng < 16; ng++) {
        const int col = ng * 8 + tig * 2;
        *(float2*)(Cb + cr0 * D + col)       = make_float2(oacc[ng][0] * i0, oacc[ng][1] * i0);
        *(float2*)(Cb + (cr0 + 8) * D + col) = make_float2(oacc[ng][2] * i1, oacc[ng][3] * i1);
    }
}

// ------------------------------------------------------------------ batched weight transpose
__global__ void transpose_all_kernel(const float* __restrict__ We, const float* __restrict__ Ws,
                                     const float* __restrict__ Wq, const float* __restrict__ Wk,
                                     const float* __restrict__ Wv,
                                     float* __restrict__ wet, float* __restrict__ wst,
                                     float* __restrict__ wqkv)
{
    __shared__ float t[32][33];
    const int z = blockIdx.z;
    const float* in; float* out; int R, C;
    switch (z) {
        case 0: in = We; out = wet;              R = D;  C = D2; break;
        case 1: in = Ws; out = wst;              R = D2; C = D;  break;
        case 2: in = Wq; out = wqkv + 0 * D * D; R = D;  C = D;  break;
        case 3: in = Wk; out = wqkv + 1 * D * D; R = D;  C = D;  break;
        default: in = Wv; out = wqkv + 2 * D * D; R = D; C = D;  break;
    }
    const int bx = blockIdx.x * 32, by = blockIdx.y * 32;
    if (bx >= C || by >= R) return;
    const int tx = threadIdx.x, ty = threadIdx.y;
#pragma unroll
    for (int dy = 0; dy < 32; dy += 8)
        t[ty + dy][tx] = in[(size_t)(by + ty + dy) * C + bx + tx];
    __syncthreads();
#pragma unroll
    for (int dy = 0; dy < 32; dy += 8)
        out[(size_t)(bx + ty + dy) * R + by + tx] = t[tx][ty + dy];
}

// ------------------------------------------------------------------ LayerNorm: 1 warp per row, shfl-only
// block = 256 threads = 8 warps = 8 rows; each lane holds 16 elems (4 float4).
__global__ void __launch_bounds__(256)
ln_kernel(const float* __restrict__ x, const float* __restrict__ x2,
          const float* __restrict__ gamma, const float* __restrict__ beta,
          float* __restrict__ out)
{
    const int w = threadIdx.x >> 5, lane = threadIdx.x & 31;
    const long long row = (long long)blockIdx.x * 8 + w;
    const float* xr = x + row * D;
    const float* x2r = x2 ? x2 + row * D : nullptr;

    float4 v[4];
#pragma unroll
    for (int i = 0; i < 4; i++) {
        v[i] = *(const float4*)(xr + i * 128 + lane * 4);
        if (x2r) {
            const float4 u = *(const float4*)(x2r + i * 128 + lane * 4);
            v[i].x += u.x; v[i].y += u.y; v[i].z += u.z; v[i].w += u.w;
        }
    }

    float s = 0.f;
#pragma unroll
    for (int i = 0; i < 4; i++) s += v[i].x + v[i].y + v[i].z + v[i].w;
#pragma unroll
    for (int o = 16; o > 0; o >>= 1) s += __shfl_xor_sync(0xffffffffu, s, o);
    const float mean = s * (1.f / D);

    float q = 0.f;
#pragma unroll
    for (int i = 0; i < 4; i++) {
        v[i].x -= mean; v[i].y -= mean; v[i].z -= mean; v[i].w -= mean;
        q += v[i].x * v[i].x + v[i].y * v[i].y + v[i].z * v[i].z + v[i].w * v[i].w;
    }
#pragma unroll
    for (int o = 16; o > 0; o >>= 1) q += __shfl_xor_sync(0xffffffffu, q, o);
    const float inv = rsqrtf(q * (1.f / D) + LN_EPS);

    float* orow = out + row * D;
#pragma unroll
    for (int i = 0; i < 4; i++) {
        const float4 g = *(const float4*)(gamma + i * 128 + lane * 4);
        const float4 bt = *(const float4*)(beta + i * 128 + lane * 4);
        float4 o;
        o.x = v[i].x * inv * g.x + bt.x;
        o.y = v[i].y * inv * g.y + bt.y;
        o.z = v[i].z * inv * g.z + bt.z;
        o.w = v[i].w * inv * g.w + bt.w;
        *(float4*)(orow + i * 128 + lane * 4) = o;
    }
}

// ------------------------------------------------------------------ host
extern "C" void kernel_launch(void* const* d_in, const int* in_sizes, int n_in,
                              void* d_out, int out_size)
{
    const float* input   = (const float*)d_in[0];
    const float* pos     = (const float*)d_in[1];
    const float* We      = (const float*)d_in[2];
    const float* be      = (const float*)d_in[3];
    const float* Ws      = (const float*)d_in[4];
    const float* bs      = (const float*)d_in[5];
    const float* gamma   = (const float*)d_in[6];
    const float* beta    = (const float*)d_in[7];
    const float* Wq      = (const float*)d_in[8];
    const float* bq      = (const float*)d_in[9];
    const float* Wk      = (const float*)d_in[10];
    const float* bk      = (const float*)d_in[11];
    const float* Wv      = (const float*)d_in[12];
    const float* bv      = (const float*)d_in[13];
    const float* alpha_p = (const float*)d_in[14];
    float* out = (float*)d_out;

    float *h, *se_pre, *se, *qk, *vt, *ctx, *wet, *wst, *wqkv;
    cudaGetSymbolAddress((void**)&h,      g_h);
    cudaGetSymbolAddress((void**)&se_pre, g_se_pre);
    cudaGetSymbolAddress((void**)&se,     g_se);
    cudaGetSymbolAddress((void**)&qk,     g_qk);
    cudaGetSymbolAddress((void**)&vt,     g_vt);
    cudaGetSymbolAddress((void**)&ctx,    g_ctx);
    cudaGetSymbolAddress((void**)&wet,    g_wet);
    cudaGetSymbolAddress((void**)&wst,    g_wst);
    cudaGetSymbolAddress((void**)&wqkv,   g_wqkv);

    static bool attr_set = false;
    const int flash_smem = (3 * 128 * FLDA) * 4 + 128 * 16;   // 204800 B
    if (!attr_set) {
        cudaFuncSetAttribute(flash_kernel, cudaFuncAttributeMaxDynamicSharedMemorySize, flash_smem);
        attr_set = true;
    }

    // 0. all weight transposes in one launch
    transpose_all_kernel<<<dim3(32, 32, 5), dim3(32, 8)>>>(
        We, Ws, Wq, Wk, Wv, wet, wst, wqkv);

    // 1. h = relu(input @ We + be)
    mma_gemm<<<dim3(D2 / 128, M_TOT / 128, 1), 256>>>(
        input, D, 0, 0,  wet, D, 0, 0,  h, D2, 0, 0,
        be, be, be, nullptr, nullptr, -1, 1, D, 1);
    // 2. se_pre = input + h @ Ws + bs
    mma_gemm<<<dim3(D / 128, M_TOT / 128, 1), 256>>>(
        h, D2, 0, 0,  wst, D2, 0, 0,  se_pre, D, 0, 0,
        bs, bs, bs, input, nullptr, -1, 0, D2, 1);
    // 3. se = LN(se_pre)   (warp-per-row)
    ln_kernel<<<M_TOT / 8, 256>>>(se_pre, nullptr, gamma, beta, se);
    // 4. q/k/v (z=0,1,2); v written transposed into g_vt
    mma_gemm<<<dim3(D / 128, M_TOT / 128, 3), 256>>>(
        se, D, 0, 0,
        wqkv, D, (long long)D * D, 0,
        qk, D, (long long)M_TOT * D, 0,
        bq, bk, bv, nullptr, vt, 2, 0, D, 1);
    // 5-7. fused flash attention -> ctx
    flash_kernel<<<dim3(S / 128, Bb * H), 256, flash_smem>>>(
        qk, qk + (size_t)M_TOT * D, pos, alpha_p);
    // 8. out = LN(se + ctx)   (warp-per-row)
    ln_kernel<<<M_TOT / 8, 256>>>(se, ctx, gamma, beta, out);
}

// round 11
// speedup vs baseline: 1.1393x; 1.0997x over previous
#include <cuda_runtime.h>
#include <math.h>
#include <stdint.h>

#define Bb 4
#define S 2048
#define D 512
#define H 4
#define HD 128
#define M_TOT (Bb*S)      // 8192
#define D2 (2*D)          // 1024
#define LN_EPS 1e-5f

// ------------------------------------------------------------------ scratch
__device__ float g_h[(size_t)M_TOT * D2];
__device__ float g_se_pre[(size_t)M_TOT * D];
__device__ float g_se[(size_t)M_TOT * D];
__device__ float g_qk[2 * (size_t)M_TOT * D];     // q then k
__device__ float g_vt[(size_t)M_TOT * D];         // [B][D][S] (V^T per batch)
__device__ float g_ctx[(size_t)M_TOT * D];
__device__ float g_wet[1024 * 512];               // We^T [1024,512]
__device__ float g_wst[512 * 1024];               // Ws^T [512,1024]
__device__ float g_wqkv[3 * 512 * 512];           // Wq^T,Wk^T,Wv^T

// ------------------------------------------------------------------ utils
__device__ __forceinline__ uint32_t f2tf(float f) {
    uint32_t u; asm("cvt.rna.tf32.f32 %0, %1;" : "=r"(u) : "f"(f)); return u;
}

__device__ __forceinline__ void mma_tf32(float c[4], const uint32_t a[4], const uint32_t b[2]) {
    asm volatile(
        "mma.sync.aligned.m16n8k8.row.col.f32.tf32.tf32.f32 "
        "{%0,%1,%2,%3}, {%4,%5,%6,%7}, {%8,%9}, {%0,%1,%2,%3};"
        : "+f"(c[0]), "+f"(c[1]), "+f"(c[2]), "+f"(c[3])
        : "r"(a[0]), "r"(a[1]), "r"(a[2]), "r"(a[3]), "r"(b[0]), "r"(b[1]));
}

#define CP_ASYNC16(dst, src) \
    asm volatile("cp.async.ca.shared.global [%0], [%1], 16;" :: "r"(dst), "l"(src))
#define CP_COMMIT() asm volatile("cp.async.commit_group;" ::: "memory")
#define CP_WAIT1()  asm volatile("cp.async.wait_group 1;" ::: "memory")
#define CP_WAIT0()  asm volatile("cp.async.wait_group 0;" ::: "memory")

#define LDA 36    // padded smem leading dim (gemm)
#define FLDA 132  // padded smem leading dim (flash, R4-proven)

// ================================================================== GEMM path
// cp.async double-buffered staging; fragment/MMA block identical to R4.
// Operands staged as RAW fp32 bits (HW tf32 truncation; no cvt on staging path).
__device__ __forceinline__ void mma_mainloop(
    const float* __restrict__ Ap, long long lda,
    const float* __restrict__ Bp, long long ldb,
    int K, uint32_t* dsm, uint32_t sbase, float acc[4][4][4])
{
    const int tid  = threadIdx.x;
    const int w    = tid >> 5, lane = tid & 31;
    const int gid  = lane >> 2, tig = lane & 3;
    const int wm   = w & 1, wn = w >> 1;

    const int srow = tid >> 3;          // 0..31 (+32 per rep)
    const int sc4  = (tid & 7) * 4;     // col base 0..28

#define ISSUE(k0, s) do { \
    _Pragma("unroll") \
    for (int i = 0; i < 4; i++) { \
        const int r = srow + 32 * i; \
        const uint32_t da = sbase + (uint32_t)(((s) * 128 * LDA + r * LDA + sc4) * 4); \
        CP_ASYNC16(da, Ap + (long long)r * lda + (k0) + sc4); \
        const uint32_t db = sbase + (uint32_t)(((2 + (s)) * 128 * LDA + r * LDA + sc4) * 4); \
        CP_ASYNC16(db, Bp + (long long)r * ldb + (k0) + sc4); \
    } \
    CP_COMMIT(); \
} while (0)

    const int nchunk = K >> 5;
    ISSUE(0, 0);
    if (nchunk > 1) ISSUE(32, 1);

    for (int c = 0; c < nchunk; c++) {
        if (c + 1 < nchunk) CP_WAIT1(); else CP_WAIT0();
        __syncthreads();

        const uint32_t (*As)[LDA] = (const uint32_t(*)[LDA])(dsm + (c & 1) * 128 * LDA);
        const uint32_t (*Bs)[LDA] = (const uint32_t(*)[LDA])(dsm + (2 + (c & 1)) * 128 * LDA);

#pragma unroll
        for (int k8 = 0; k8 < 4; k8++) {
            const int kb = k8 * 8;
            uint32_t af[4][4], bf[4][2];
#pragma unroll
            for (int mt = 0; mt < 4; mt++) {
                const int r = wm * 64 + mt * 16 + gid;
                af[mt][0] = As[r][kb + tig];
                af[mt][1] = As[r + 8][kb + tig];
                af[mt][2] = As[r][kb + tig + 4];
                af[mt][3] = As[r + 8][kb + tig + 4];
            }
#pragma unroll
            for (int nt = 0; nt < 4; nt++) {
                const int n = wn * 32 + nt * 8 + gid;
                bf[nt][0] = Bs[n][kb + tig];
                bf[nt][1] = Bs[n][kb + tig + 4];
            }
#pragma unroll
            for (int mt = 0; mt < 4; mt++)
#pragma unroll
                for (int nt = 0; nt < 4; nt++)
                    mma_tf32(acc[mt][nt], af[mt], bf[nt]);
        }
        __syncthreads();
        if (c + 2 < nchunk) ISSUE((c + 2) << 5, c & 1);
    }
#undef ISSUE
}

__global__ void __launch_bounds__(256)
mma_gemm(const float* __restrict__ A, long long lda, long long Azb, long long Azh,
         const float* __restrict__ Bt, long long ldb, long long Bzb, long long Bzh,
         float* __restrict__ C, long long ldc, long long Czb, long long Czh,
         const float* b0, const float* b1, const float* b2,
         const float* __restrict__ resid, float* __restrict__ vt, int vt_z,
         int relu, int K, int zdiv)
{
    extern __shared__ uint32_t dsm[];
    const uint32_t sbase = (uint32_t)__cvta_generic_to_shared(dsm);

    const int tid = threadIdx.x;
    const int z = blockIdx.z;
    const long long zb = z / zdiv, zh = z % zdiv;

    const float* Ap = A + zb * Azb + zh * Azh + (long long)blockIdx.y * 128 * lda;
    const float* Bp = Bt + zb * Bzb + zh * Bzh + (long long)blockIdx.x * 128 * ldb;

    float acc[4][4][4];
#pragma unroll
    for (int i = 0; i < 4; i++)
#pragma unroll
        for (int j = 0; j < 4; j++)
#pragma unroll
            for (int e = 0; e < 4; e++) acc[i][j][e] = 0.f;

    mma_mainloop(Ap, lda, Bp, ldb, K, dsm, sbase, acc);

    const float* bias = (z == 0) ? b0 : (z == 1) ? b1 : b2;
    const int w = tid >> 5, lane = tid & 31;
    const int gid = lane >> 2, tig = lane & 3;
    const int wm = w & 1, wn = w >> 1;
    float* Cz = C + zb * Czb + zh * Czh;
    const bool dotrans = (vt != nullptr) && (z == vt_z);

#pragma unroll
    for (int mt = 0; mt < 4; mt++) {
        const long long r0 = (long long)blockIdx.y * 128 + wm * 64 + mt * 16 + gid;
        const long long r1 = r0 + 8;
#pragma unroll
        for (int nt = 0; nt < 4; nt++) {
            const long long cb = (long long)blockIdx.x * 128 + wn * 32 + nt * 8 + tig * 2;
            float v0 = acc[mt][nt][0], v1 = acc[mt][nt][1];
            float v2 = acc[mt][nt][2], v3 = acc[mt][nt][3];
            if (bias) {
                const float bx = __ldg(bias + cb), by = __ldg(bias + cb + 1);
                v0 += bx; v1 += by; v2 += bx; v3 += by;
            }
            if (resid) {
                const float2 q0 = *(const float2*)(resid + r0 * ldc + cb);
                const float2 q1 = *(const float2*)(resid + r1 * ldc + cb);
                v0 += q0.x; v1 += q0.y; v2 += q1.x; v3 += q1.y;
            }
            if (relu) {
                v0 = fmaxf(v0, 0.f); v1 = fmaxf(v1, 0.f);
                v2 = fmaxf(v2, 0.f); v3 = fmaxf(v3, 0.f);
            }
            if (dotrans) {
                const long long b0r = r0 >> 11, s0 = r0 & (S - 1);
                const long long b1r = r1 >> 11, s1 = r1 & (S - 1);
                float* vb0 = vt + b0r * ((long long)D * S);
                float* vb1 = vt + b1r * ((long long)D * S);
                vb0[cb * S + s0] = v0; vb0[(cb + 1) * S + s0] = v1;
                vb1[cb * S + s1] = v2; vb1[(cb + 1) * S + s1] = v3;
            } else {
                *(float2*)(Cz + r0 * ldc + cb) = make_float2(v0, v1);
                *(float2*)(Cz + r1 * ldc + cb) = make_float2(v2, v3);
            }
        }
    }
}

// ================================================================== flash attention (R4 verbatim)
__global__ void __launch_bounds__(256)
flash_kernel(const float* __restrict__ qbase, const float* __restrict__ kbase,
             const float* __restrict__ pos, const float* __restrict__ alpha_p)
{
    extern __shared__ uint32_t sm[];
    uint32_t (*Qs)[FLDA] = (uint32_t(*)[FLDA])sm;
    uint32_t (*Ks)[FLDA] = (uint32_t(*)[FLDA])(sm + 128 * FLDA);
    uint32_t (*Vs)[FLDA] = (uint32_t(*)[FLDA])(sm + 2 * 128 * FLDA);
    float4* spos = (float4*)(sm + 3 * 128 * FLDA);

    const int tid  = threadIdx.x;
    const int w    = tid >> 5, lane = tid & 31;
    const int gid  = lane >> 2, tig = lane & 3;
    const int z    = blockIdx.y;
    const long long b = z / H, h = z % H;
    const int qt   = blockIdx.x;

    const float* Qp = qbase + b * ((long long)S * D) + h * HD + (long long)qt * 128 * D;
    const float* Kb = kbase + b * ((long long)S * D) + h * HD;
    const float* Vb = g_vt + b * ((long long)D * S) + (long long)h * HD * S;  // [hd][s]
    const float* pb = pos + b * ((long long)S * 3);

    // stage Q tile (tf32)
#pragma unroll
    for (int i = 0; i < 16; i++) {
        const int r = w + 8 * i;
        const float4 v = *(const float4*)(Qp + (long long)r * D + lane * 4);
        uint32_t* dst = &Qs[r][lane * 4];
        dst[0] = f2tf(v.x); dst[1] = f2tf(v.y); dst[2] = f2tf(v.z); dst[3] = f2tf(v.w);
    }

    const long long gr0 = (long long)qt * 128 + w * 16 + gid;
    const long long gr1 = gr0 + 8;
    const float px0 = __ldg(pb + gr0 * 3), py0 = __ldg(pb + gr0 * 3 + 1), pz0 = __ldg(pb + gr0 * 3 + 2);
    const float px1 = __ldg(pb + gr1 * 3), py1 = __ldg(pb + gr1 * 3 + 1), pz1 = __ldg(pb + gr1 * 3 + 2);
    const float sq0 = px0 * px0 + py0 * py0 + pz0 * pz0;
    const float sq1 = px1 * px1 + py1 * py1 + pz1 * pz1;

    float oacc[16][4];
#pragma unroll
    for (int i = 0; i < 16; i++)
#pragma unroll
        for (int e = 0; e < 4; e++) oacc[i][e] = 0.f;
    float m0 = -1e30f, m1 = -1e30f, l0 = 0.f, l1 = 0.f;

    const float scale = 0.08838834764831845f;  // 1/sqrt(128)
    const float alpha = __ldg(alpha_p);
    const int src0 = (lane & ~3) | (tig >> 1);
    const int src1 = src0 + 2;
    const bool odd = (tig & 1);

    for (int j = 0; j < 16; j++) {
        __syncthreads();
        const float* Kp = Kb + (long long)j * 128 * D;
#pragma unroll
        for (int i = 0; i < 16; i++) {
            const int r = w + 8 * i;
            const float4 v = *(const float4*)(Kp + (long long)r * D + lane * 4);
            uint32_t* dk = &Ks[r][lane * 4];
            dk[0] = f2tf(v.x); dk[1] = f2tf(v.y); dk[2] = f2tf(v.z); dk[3] = f2tf(v.w);
            const float4 u = *(const float4*)(Vb + (long long)r * S + j * 128 + lane * 4);
            uint32_t* dv = &Vs[r][lane * 4];
            dv[0] = f2tf(u.x); dv[1] = f2tf(u.y); dv[2] = f2tf(u.z); dv[3] = f2tf(u.w);
        }
        if (tid < 128) {
            const long long c = (long long)j * 128 + tid;
            const float x = pb[c * 3], y = pb[c * 3 + 1], zz = pb[c * 3 + 2];
            spos[tid] = make_float4(x, y, zz, x * x + y * y + zz * zz);
        }
        __syncthreads();

        // ---- S = Q @ K^T ----
        float sacc[16][4];
#pragma unroll
        for (int i = 0; i < 16; i++)
#pragma unroll
            for (int e = 0; e < 4; e++) sacc[i][e] = 0.f;

        const int ra = w * 16 + gid;
#pragma unroll
        for (int g = 0; g < 16; g++) {
            const int kb = g * 8;
            uint32_t af[4];
            af[0] = Qs[ra][kb + tig];
            af[1] = Qs[ra + 8][kb + tig];
            af[2] = Qs[ra][kb + tig + 4];
            af[3] = Qs[ra + 8][kb + tig + 4];
#pragma unroll
            for (int nt = 0; nt < 16; nt++) {
                uint32_t bf[2] = { Ks[nt * 8 + gid][kb + tig], Ks[nt * 8 + gid][kb + tig + 4] };
                mma_tf32(sacc[nt], af, bf);
            }
        }

        // ---- bias + online softmax ----
        float nm0 = m0, nm1 = m1;
#pragma unroll
        for (int nt = 0; nt < 16; nt++) {
            const int c0 = nt * 8 + tig * 2;
            const float4 q0 = spos[c0];
            const float4 q1 = spos[c0 + 1];
            float d;
            d = fmaxf(sq0 + q0.w - 2.f * (px0 * q0.x + py0 * q0.y + pz0 * q0.z), 0.f);
            sacc[nt][0] = sacc[nt][0] * scale - alpha * d;
            d = fmaxf(sq0 + q1.w - 2.f * (px0 * q1.x + py0 * q1.y + pz0 * q1.z), 0.f);
            sacc[nt][1] = sacc[nt][1] * scale - alpha * d;
            d = fmaxf(sq1 + q0.w - 2.f * (px1 * q0.x + py1 * q0.y + pz1 * q0.z), 0.f);
            sacc[nt][2] = sacc[nt][2] * scale - alpha * d;
            d = fmaxf(sq1 + q1.w - 2.f * (px1 * q1.x + py1 * q1.y + pz1 * q1.z), 0.f);
            sacc[nt][3] = sacc[nt][3] * scale - alpha * d;
            nm0 = fmaxf(nm0, fmaxf(sacc[nt][0], sacc[nt][1]));
            nm1 = fmaxf(nm1, fmaxf(sacc[nt][2], sacc[nt][3]));
        }
        nm0 = fmaxf(nm0, __shfl_xor_sync(0xffffffffu, nm0, 1));
        nm0 = fmaxf(nm0, __shfl_xor_sync(0xffffffffu, nm0, 2));
        nm1 = fmaxf(nm1, __shfl_xor_sync(0xffffffffu, nm1, 1));
        nm1 = fmaxf(nm1, __shfl_xor_sync(0xffffffffu, nm1, 2));

        const float f0 = __expf(m0 - nm0);
        const float f1 = __expf(m1 - nm1);
        m0 = nm0; m1 = nm1;

        float rs0 = 0.f, rs1 = 0.f;
#pragma unroll
        for (int nt = 0; nt < 16; nt++) {
            sacc[nt][0] = __expf(sacc[nt][0] - nm0);
            sacc[nt][1] = __expf(sacc[nt][1] - nm0);
            sacc[nt][2] = __expf(sacc[nt][2] - nm1);
            sacc[nt][3] = __expf(sacc[nt][3] - nm1);
            rs0 += sacc[nt][0] + sacc[nt][1];
            rs1 += sacc[nt][2] + sacc[nt][3];
        }
        rs0 += __shfl_xor_sync(0xffffffffu, rs0, 1);
        rs0 += __shfl_xor_sync(0xffffffffu, rs0, 2);
        rs1 += __shfl_xor_sync(0xffffffffu, rs1, 1);
        rs1 += __shfl_xor_sync(0xffffffffu, rs1, 2);
        l0 = l0 * f0 + rs0;
        l1 = l1 * f1 + rs1;

#pragma unroll
        for (int i = 0; i < 16; i++) {
            oacc[i][0] *= f0; oacc[i][1] *= f0;
            oacc[i][2] *= f1; oacc[i][3] *= f1;
        }

        // ---- O += P @ V ----
#pragma unroll
        for (int g = 0; g < 16; g++) {
            const float u00 = __shfl_sync(0xffffffffu, sacc[g][0], src0);
            const float u01 = __shfl_sync(0xffffffffu, sacc[g][1], src0);
            const float u10 = __shfl_sync(0xffffffffu, sacc[g][0], src1);
            const float u11 = __shfl_sync(0xffffffffu, sacc[g][1], src1);
            const float u20 = __shfl_sync(0xffffffffu, sacc[g][2], src0);
            const float u21 = __shfl_sync(0xffffffffu, sacc[g][3], src0);
            const float u30 = __shfl_sync(0xffffffffu, sacc[g][2], src1);
            const float u31 = __shfl_sync(0xffffffffu, sacc[g][3], src1);
            uint32_t af[4];
            af[0] = f2tf(odd ? u01 : u00);   // P[row0][tig]
            af[1] = f2tf(odd ? u21 : u20);   // P[row1][tig]
            af[2] = f2tf(odd ? u11 : u10);   // P[row0][tig+4]
            af[3] = f2tf(odd ? u31 : u30);   // P[row1][tig+4]
            const int kb = g * 8;
#pragma unroll
            for (int ng = 0; ng < 16; ng++) {
                uint32_t bf[2] = { Vs[ng * 8 + gid][kb + tig], Vs[ng * 8 + gid][kb + tig + 4] };
                mma_tf32(oacc[ng], af, bf);
            }
        }
    }

    // ---- epilogue: O / l -> ctx ----
    const float i0 = 1.f / l0, i1 = 1.f / l1;
    float* Cb = g_ctx + b * ((long long)S * D) + h * HD;
    const long long cr0 = (long long)qt * 128 + w * 16 + gid;
#pragma unroll
    for (int ng = 0; ng < 16; ng++) {
        const int col = ng * 8 + tig * 2;
        *(float2*)(Cb + cr0 * D + col)       = make_float2(oacc[ng][0] * i0, oacc[ng][1] * i0);
        *(float2*)(Cb + (cr0 + 8) * D + col) = make_float2(oacc[ng][2] * i1, oacc[ng][3] * i1);
    }
}

// ------------------------------------------------------------------ batched weight transpose
__global__ void transpose_all_kernel(const float* __restrict__ We, const float* __restrict__ Ws,
                                     const float* __restrict__ Wq, const float* __restrict__ Wk,
                                     const float* __restrict__ Wv,
                                     float* __restrict__ wet, float* __restrict__ wst,
                                     float* __restrict__ wqkv)
{
    __shared__ float t[32][33];
    const int z = blockIdx.z;
    const float* in; float* out; int R, C;
    switch (z) {
        case 0: in = We; out = wet;              R = D;  C = D2; break;
        case 1: in = Ws; out = wst;              R = D2; C = D;  break;
        case 2: in = Wq; out = wqkv + 0 * D * D; R = D;  C = D;  break;
        case 3: in = Wk; out = wqkv + 1 * D * D; R = D;  C = D;  break;
        default: in = Wv; out = wqkv + 2 * D * D; R = D; C = D;  break;
    }
    const int bx = blockIdx.x * 32, by = blockIdx.y * 32;
    if (bx >= C || by >= R) return;
    const int tx = threadIdx.x, ty = threadIdx.y;
#pragma unroll
    for (int dy = 0; dy < 32; dy += 8)
        t[ty + dy][tx] = in[(size_t)(by + ty + dy) * C + bx + tx];
    __syncthreads();
#pragma unroll
    for (int dy = 0; dy < 32; dy += 8)
        out[(size_t)(bx + ty + dy) * R + by + tx] = t[tx][ty + dy];
}

// ------------------------------------------------------------------ LayerNorm: 1 warp per row (R10)
__global__ void __launch_bounds__(256)
ln_kernel(const float* __restrict__ x, const float* __restrict__ x2,
          const float* __restrict__ gamma, const float* __restrict__ beta,
          float* __restrict__ out)
{
    const int w = threadIdx.x >> 5, lane = threadIdx.x & 31;
    const long long row = (long long)blockIdx.x * 8 + w;
    const float* xr = x + row * D;
    const float* x2r = x2 ? x2 + row * D : nullptr;

    float4 v[4];
#pragma unroll
    for (int i = 0; i < 4; i++) {
        v[i] = *(const float4*)(xr + i * 128 + lane * 4);
        if (x2r) {
            const float4 u = *(const float4*)(x2r + i * 128 + lane * 4);
            v[i].x += u.x; v[i].y += u.y; v[i].z += u.z; v[i].w += u.w;
        }
    }

    float s = 0.f;
#pragma unroll
    for (int i = 0; i < 4; i++) s += v[i].x + v[i].y + v[i].z + v[i].w;
#pragma unroll
    for (int o = 16; o > 0; o >>= 1) s += __shfl_xor_sync(0xffffffffu, s, o);
    const float mean = s * (1.f / D);

    float q = 0.f;
#pragma unroll
    for (int i = 0; i < 4; i++) {
        v[i].x -= mean; v[i].y -= mean; v[i].z -= mean; v[i].w -= mean;
        q += v[i].x * v[i].x + v[i].y * v[i].y + v[i].z * v[i].z + v[i].w * v[i].w;
    }
#pragma unroll
    for (int o = 16; o > 0; o >>= 1) q += __shfl_xor_sync(0xffffffffu, q, o);
    const float inv = rsqrtf(q * (1.f / D) + LN_EPS);

    float* orow = out + row * D;
#pragma unroll
    for (int i = 0; i < 4; i++) {
        const float4 g = *(const float4*)(gamma + i * 128 + lane * 4);
        const float4 bt = *(const float4*)(beta + i * 128 + lane * 4);
        float4 o;
        o.x = v[i].x * inv * g.x + bt.x;
        o.y = v[i].y * inv * g.y + bt.y;
        o.z = v[i].z * inv * g.z + bt.z;
        o.w = v[i].w * inv * g.w + bt.w;
        *(float4*)(orow + i * 128 + lane * 4) = o;
    }
}

// ------------------------------------------------------------------ host
extern "C" void kernel_launch(void* const* d_in, const int* in_sizes, int n_in,
                              void* d_out, int out_size)
{
    const float* input   = (const float*)d_in[0];
    const float* pos     = (const float*)d_in[1];
    const float* We      = (const float*)d_in[2];
    const float* be      = (const float*)d_in[3];
    const float* Ws      = (const float*)d_in[4];
    const float* bs      = (const float*)d_in[5];
    const float* gamma   = (const float*)d_in[6];
    const float* beta    = (const float*)d_in[7];
    const float* Wq      = (const float*)d_in[8];
    const float* bq      = (const float*)d_in[9];
    const float* Wk      = (const float*)d_in[10];
    const float* bk      = (const float*)d_in[11];
    const float* Wv      = (const float*)d_in[12];
    const float* bv      = (const float*)d_in[13];
    const float* alpha_p = (const float*)d_in[14];
    float* out = (float*)d_out;

    float *h, *se_pre, *se, *qk, *vt, *ctx, *wet, *wst, *wqkv;
    cudaGetSymbolAddress((void**)&h,      g_h);
    cudaGetSymbolAddress((void**)&se_pre, g_se_pre);
    cudaGetSymbolAddress((void**)&se,     g_se);
    cudaGetSymbolAddress((void**)&qk,     g_qk);
    cudaGetSymbolAddress((void**)&vt,     g_vt);
    cudaGetSymbolAddress((void**)&ctx,    g_ctx);
    cudaGetSymbolAddress((void**)&wet,    g_wet);
    cudaGetSymbolAddress((void**)&wst,    g_wst);
    cudaGetSymbolAddress((void**)&wqkv,   g_wqkv);

    const int gemm_smem  = 4 * 128 * LDA * 4;                // 73728 B (double-buffered A+B)
    const int flash_smem = (3 * 128 * FLDA) * 4 + 128 * 16;  // 204800 B
    static bool attr_set = false;
    if (!attr_set) {
        cudaFuncSetAttribute(flash_kernel, cudaFuncAttributeMaxDynamicSharedMemorySize, flash_smem);
        cudaFuncSetAttribute(mma_gemm,     cudaFuncAttributeMaxDynamicSharedMemorySize, gemm_smem);
        attr_set = true;
    }

    // 0. all weight transposes in one launch
    transpose_all_kernel<<<dim3(32, 32, 5), dim3(32, 8)>>>(
        We, Ws, Wq, Wk, Wv, wet, wst, wqkv);

    // 1. h = relu(input @ We + be)
    mma_gemm<<<dim3(D2 / 128, M_TOT / 128, 1), 256, gemm_smem>>>(
        input, D, 0, 0,  wet, D, 0, 0,  h, D2, 0, 0,
        be, be, be, nullptr, nullptr, -1, 1, D, 1);
    // 2. se_pre = input + h @ Ws + bs
    mma_gemm<<<dim3(D / 128, M_TOT / 128, 1), 256, gemm_smem>>>(
        h, D2, 0, 0,  wst, D2, 0, 0,  se_pre, D, 0, 0,
        bs, bs, bs, input, nullptr, -1, 0, D2, 1);
    // 3. se = LN(se_pre)   (warp-per-row)
    ln_kernel<<<M_TOT / 8, 256>>>(se_pre, nullptr, gamma, beta, se);
    // 4. q/k/v (z=0,1,2); v written transposed into g_vt
    mma_gemm<<<dim3(D / 128, M_TOT / 128, 3), 256, gemm_smem>>>(
        se, D, 0, 0,
        wqkv, D, (long long)D * D, 0,
        qk, D, (long long)M_TOT * D, 0,
        bq, bk, bv, nullptr, vt, 2, 0, D, 1);
    // 5-7. fused flash attention -> ctx
    flash_kernel<<<dim3(S / 128, Bb * H), 256, flash_smem>>>(
        qk, qk + (size_t)M_TOT * D, pos, alpha_p);
    // 8. out = LN(se + ctx)   (warp-per-row)
    ln_kernel<<<M_TOT / 8, 256>>>(se, ctx, gamma, beta, out);
}

// round 12
// speedup vs baseline: 1.2171x; 1.0683x over previous
#include <cuda_runtime.h>
#include <math.h>
#include <stdint.h>

#define Bb 4
#define S 2048
#define D 512
#define H 4
#define HD 128
#define M_TOT (Bb*S)      // 8192
#define D2 (2*D)          // 1024
#define LN_EPS 1e-5f

// ------------------------------------------------------------------ scratch
__device__ float g_h[(size_t)M_TOT * D2];
__device__ float g_se_pre[(size_t)M_TOT * D];
__device__ float g_se[(size_t)M_TOT * D];
__device__ float g_qk[2 * (size_t)M_TOT * D];     // q then k
__device__ float g_vt[(size_t)M_TOT * D];         // [B][D][S] (V^T per batch)
__device__ float g_ctx[(size_t)M_TOT * D];
__device__ float g_wet[1024 * 512];               // We^T [1024,512]
__device__ float g_wst[512 * 1024];               // Ws^T [512,1024]
__device__ float g_wqkv[3 * 512 * 512];           // Wq^T,Wk^T,Wv^T

// ------------------------------------------------------------------ utils
__device__ __forceinline__ uint32_t f2tf(float f) {
    uint32_t u; asm("cvt.rna.tf32.f32 %0, %1;" : "=r"(u) : "f"(f)); return u;
}

__device__ __forceinline__ void mma_tf32(float c[4], const uint32_t a[4], const uint32_t b[2]) {
    asm volatile(
        "mma.sync.aligned.m16n8k8.row.col.f32.tf32.tf32.f32 "
        "{%0,%1,%2,%3}, {%4,%5,%6,%7}, {%8,%9}, {%0,%1,%2,%3};"
        : "+f"(c[0]), "+f"(c[1]), "+f"(c[2]), "+f"(c[3])
        : "r"(a[0]), "r"(a[1]), "r"(a[2]), "r"(a[3]), "r"(b[0]), "r"(b[1]));
}

#define CP_ASYNC16(dst, src) \
    asm volatile("cp.async.ca.shared.global [%0], [%1], 16;" :: "r"(dst), "l"(src))
#define CP_COMMIT() asm volatile("cp.async.commit_group;" ::: "memory")
#define CP_WAIT1()  asm volatile("cp.async.wait_group 1;" ::: "memory")
#define CP_WAIT0()  asm volatile("cp.async.wait_group 0;" ::: "memory")

#define LDA 36    // padded smem leading dim (gemm)
#define FLDA 132  // padded smem leading dim (flash); row = 528 B (16B-aligned)

// ================================================================== GEMM path (R11 verbatim)
__device__ __forceinline__ void mma_mainloop(
    const float* __restrict__ Ap, long long lda,
    const float* __restrict__ Bp, long long ldb,
    int K, uint32_t* dsm, uint32_t sbase, float acc[4][4][4])
{
    const int tid  = threadIdx.x;
    const int w    = tid >> 5, lane = tid & 31;
    const int gid  = lane >> 2, tig = lane & 3;
    const int wm   = w & 1, wn = w >> 1;

    const int srow = tid >> 3;
    const int sc4  = (tid & 7) * 4;

#define ISSUE(k0, s) do { \
    _Pragma("unroll") \
    for (int i = 0; i < 4; i++) { \
        const int r = srow + 32 * i; \
        const uint32_t da = sbase + (uint32_t)(((s) * 128 * LDA + r * LDA + sc4) * 4); \
        CP_ASYNC16(da, Ap + (long long)r * lda + (k0) + sc4); \
        const uint32_t db = sbase + (uint32_t)(((2 + (s)) * 128 * LDA + r * LDA + sc4) * 4); \
        CP_ASYNC16(db, Bp + (long long)r * ldb + (k0) + sc4); \
    } \
    CP_COMMIT(); \
} while (0)

    const int nchunk = K >> 5;
    ISSUE(0, 0);
    if (nchunk > 1) ISSUE(32, 1);

    for (int c = 0; c < nchunk; c++) {
        if (c + 1 < nchunk) CP_WAIT1(); else CP_WAIT0();
        __syncthreads();

        const uint32_t (*As)[LDA] = (const uint32_t(*)[LDA])(dsm + (c & 1) * 128 * LDA);
        const uint32_t (*Bs)[LDA] = (const uint32_t(*)[LDA])(dsm + (2 + (c & 1)) * 128 * LDA);

#pragma unroll
        for (int k8 = 0; k8 < 4; k8++) {
            const int kb = k8 * 8;
            uint32_t af[4][4], bf[4][2];
#pragma unroll
            for (int mt = 0; mt < 4; mt++) {
                const int r = wm * 64 + mt * 16 + gid;
                af[mt][0] = As[r][kb + tig];
                af[mt][1] = As[r + 8][kb + tig];
                af[mt][2] = As[r][kb + tig + 4];
                af[mt][3] = As[r + 8][kb + tig + 4];
            }
#pragma unroll
            for (int nt = 0; nt < 4; nt++) {
                const int n = wn * 32 + nt * 8 + gid;
                bf[nt][0] = Bs[n][kb + tig];
                bf[nt][1] = Bs[n][kb + tig + 4];
            }
#pragma unroll
            for (int mt = 0; mt < 4; mt++)
#pragma unroll
                for (int nt = 0; nt < 4; nt++)
                    mma_tf32(acc[mt][nt], af[mt], bf[nt]);
        }
        __syncthreads();
        if (c + 2 < nchunk) ISSUE((c + 2) << 5, c & 1);
    }
#undef ISSUE
}

__global__ void __launch_bounds__(256)
mma_gemm(const float* __restrict__ A, long long lda, long long Azb, long long Azh,
         const float* __restrict__ Bt, long long ldb, long long Bzb, long long Bzh,
         float* __restrict__ C, long long ldc, long long Czb, long long Czh,
         const float* b0, const float* b1, const float* b2,
         const float* __restrict__ resid, float* __restrict__ vt, int vt_z,
         int relu, int K, int zdiv)
{
    extern __shared__ uint32_t dsm[];
    const uint32_t sbase = (uint32_t)__cvta_generic_to_shared(dsm);

    const int tid = threadIdx.x;
    const int z = blockIdx.z;
    const long long zb = z / zdiv, zh = z % zdiv;

    const float* Ap = A + zb * Azb + zh * Azh + (long long)blockIdx.y * 128 * lda;
    const float* Bp = Bt + zb * Bzb + zh * Bzh + (long long)blockIdx.x * 128 * ldb;

    float acc[4][4][4];
#pragma unroll
    for (int i = 0; i < 4; i++)
#pragma unroll
        for (int j = 0; j < 4; j++)
#pragma unroll
            for (int e = 0; e < 4; e++) acc[i][j][e] = 0.f;

    mma_mainloop(Ap, lda, Bp, ldb, K, dsm, sbase, acc);

    const float* bias = (z == 0) ? b0 : (z == 1) ? b1 : b2;
    const int w = tid >> 5, lane = tid & 31;
    const int gid = lane >> 2, tig = lane & 3;
    const int wm = w & 1, wn = w >> 1;
    float* Cz = C + zb * Czb + zh * Czh;
    const bool dotrans = (vt != nullptr) && (z == vt_z);

#pragma unroll
    for (int mt = 0; mt < 4; mt++) {
        const long long r0 = (long long)blockIdx.y * 128 + wm * 64 + mt * 16 + gid;
        const long long r1 = r0 + 8;
#pragma unroll
        for (int nt = 0; nt < 4; nt++) {
            const long long cb = (long long)blockIdx.x * 128 + wn * 32 + nt * 8 + tig * 2;
            float v0 = acc[mt][nt][0], v1 = acc[mt][nt][1];
            float v2 = acc[mt][nt][2], v3 = acc[mt][nt][3];
            if (bias) {
                const float bx = __ldg(bias + cb), by = __ldg(bias + cb + 1);
                v0 += bx; v1 += by; v2 += bx; v3 += by;
            }
            if (resid) {
                const float2 q0 = *(const float2*)(resid + r0 * ldc + cb);
                const float2 q1 = *(const float2*)(resid + r1 * ldc + cb);
                v0 += q0.x; v1 += q0.y; v2 += q1.x; v3 += q1.y;
            }
            if (relu) {
                v0 = fmaxf(v0, 0.f); v1 = fmaxf(v1, 0.f);
                v2 = fmaxf(v2, 0.f); v3 = fmaxf(v3, 0.f);
            }
            if (dotrans) {
                const long long b0r = r0 >> 11, s0 = r0 & (S - 1);
                const long long b1r = r1 >> 11, s1 = r1 & (S - 1);
                float* vb0 = vt + b0r * ((long long)D * S);
                float* vb1 = vt + b1r * ((long long)D * S);
                vb0[cb * S + s0] = v0; vb0[(cb + 1) * S + s0] = v1;
                vb1[cb * S + s1] = v2; vb1[(cb + 1) * S + s1] = v3;
            } else {
                *(float2*)(Cz + r0 * ldc + cb) = make_float2(v0, v1);
                *(float2*)(Cz + r1 * ldc + cb) = make_float2(v2, v3);
            }
        }
    }
}

// ================================================================== flash attention
// K/V staging via cp.async (raw fp32, HW tf32 truncation); structure otherwise R4.
__global__ void __launch_bounds__(256)
flash_kernel(const float* __restrict__ qbase, const float* __restrict__ kbase,
             const float* __restrict__ pos, const float* __restrict__ alpha_p)
{
    extern __shared__ uint32_t sm[];
    uint32_t (*Qs)[FLDA] = (uint32_t(*)[FLDA])sm;
    uint32_t (*Ks)[FLDA] = (uint32_t(*)[FLDA])(sm + 128 * FLDA);
    uint32_t (*Vs)[FLDA] = (uint32_t(*)[FLDA])(sm + 2 * 128 * FLDA);
    float4* spos = (float4*)(sm + 3 * 128 * FLDA);
    const uint32_t sbase = (uint32_t)__cvta_generic_to_shared(sm);

    const int tid  = threadIdx.x;
    const int w    = tid >> 5, lane = tid & 31;
    const int gid  = lane >> 2, tig = lane & 3;
    const int z    = blockIdx.y;
    const long long b = z / H, h = z % H;
    const int qt   = blockIdx.x;

    const float* Qp = qbase + b * ((long long)S * D) + h * HD + (long long)qt * 128 * D;
    const float* Kb = kbase + b * ((long long)S * D) + h * HD;
    const float* Vb = g_vt + b * ((long long)D * S) + (long long)h * HD * S;  // [hd][s]
    const float* pb = pos + b * ((long long)S * 3);

    // stage Q tile (tf32, rna — loaded once)
#pragma unroll
    for (int i = 0; i < 16; i++) {
        const int r = w + 8 * i;
        const float4 v = *(const float4*)(Qp + (long long)r * D + lane * 4);
        uint32_t* dst = &Qs[r][lane * 4];
        dst[0] = f2tf(v.x); dst[1] = f2tf(v.y); dst[2] = f2tf(v.z); dst[3] = f2tf(v.w);
    }

    const long long gr0 = (long long)qt * 128 + w * 16 + gid;
    const long long gr1 = gr0 + 8;
    const float px0 = __ldg(pb + gr0 * 3), py0 = __ldg(pb + gr0 * 3 + 1), pz0 = __ldg(pb + gr0 * 3 + 2);
    const float px1 = __ldg(pb + gr1 * 3), py1 = __ldg(pb + gr1 * 3 + 1), pz1 = __ldg(pb + gr1 * 3 + 2);
    const float sq0 = px0 * px0 + py0 * py0 + pz0 * pz0;
    const float sq1 = px1 * px1 + py1 * py1 + pz1 * pz1;

    float oacc[16][4];
#pragma unroll
    for (int i = 0; i < 16; i++)
#pragma unroll
        for (int e = 0; e < 4; e++) oacc[i][e] = 0.f;
    float m0 = -1e30f, m1 = -1e30f, l0 = 0.f, l1 = 0.f;

    const float scale = 0.08838834764831845f;  // 1/sqrt(128)
    const float alpha = __ldg(alpha_p);
    const int src0 = (lane & ~3) | (tig >> 1);
    const int src1 = src0 + 2;
    const bool odd = (tig & 1);

    for (int j = 0; j < 16; j++) {
        __syncthreads();   // previous tile fully consumed
        const float* Kp = Kb + (long long)j * 128 * D;
        const float* Vp = Vb + (long long)j * 128;
#pragma unroll
        for (int i = 0; i < 16; i++) {
            const int r = w + 8 * i;
            const uint32_t dk = sbase + (uint32_t)((128 * FLDA + r * FLDA + lane * 4) * 4);
            CP_ASYNC16(dk, Kp + (long long)r * D + lane * 4);
            const uint32_t dv = sbase + (uint32_t)((2 * 128 * FLDA + r * FLDA + lane * 4) * 4);
            CP_ASYNC16(dv, Vp + (long long)r * S + lane * 4);
        }
        CP_COMMIT();
        if (tid < 128) {
            const long long c = (long long)j * 128 + tid;
            const float x = pb[c * 3], y = pb[c * 3 + 1], zz = pb[c * 3 + 2];
            spos[tid] = make_float4(x, y, zz, x * x + y * y + zz * zz);
        }
        CP_WAIT0();
        __syncthreads();

        // ---- S = Q @ K^T ----
        float sacc[16][4];
#pragma unroll
        for (int i = 0; i < 16; i++)
#pragma unroll
            for (int e = 0; e < 4; e++) sacc[i][e] = 0.f;

        const int ra = w * 16 + gid;
#pragma unroll
        for (int g = 0; g < 16; g++) {
            const int kb = g * 8;
            uint32_t af[4];
            af[0] = Qs[ra][kb + tig];
            af[1] = Qs[ra + 8][kb + tig];
            af[2] = Qs[ra][kb + tig + 4];
            af[3] = Qs[ra + 8][kb + tig + 4];
#pragma unroll
            for (int nt = 0; nt < 16; nt++) {
                uint32_t bf[2] = { Ks[nt * 8 + gid][kb + tig], Ks[nt * 8 + gid][kb + tig + 4] };
                mma_tf32(sacc[nt], af, bf);
            }
        }

        // ---- bias + online softmax ----
        float nm0 = m0, nm1 = m1;
#pragma unroll
        for (int nt = 0; nt < 16; nt++) {
            const int c0 = nt * 8 + tig * 2;
            const float4 q0 = spos[c0];
            const float4 q1 = spos[c0 + 1];
            float d;
            d = fmaxf(sq0 + q0.w - 2.f * (px0 * q0.x + py0 * q0.y + pz0 * q0.z), 0.f);
            sacc[nt][0] = sacc[nt][0] * scale - alpha * d;
            d = fmaxf(sq0 + q1.w - 2.f * (px0 * q1.x + py0 * q1.y + pz0 * q1.z), 0.f);
            sacc[nt][1] = sacc[nt][1] * scale - alpha * d;
            d = fmaxf(sq1 + q0.w - 2.f * (px1 * q0.x + py1 * q0.y + pz1 * q0.z), 0.f);
            sacc[nt][2] = sacc[nt][2] * scale - alpha * d;
            d = fmaxf(sq1 + q1.w - 2.f * (px1 * q1.x + py1 * q1.y + pz1 * q1.z), 0.f);
            sacc[nt][3] = sacc[nt][3] * scale - alpha * d;
            nm0 = fmaxf(nm0, fmaxf(sacc[nt][0], sacc[nt][1]));
            nm1 = fmaxf(nm1, fmaxf(sacc[nt][2], sacc[nt][3]));
        }
        nm0 = fmaxf(nm0, __shfl_xor_sync(0xffffffffu, nm0, 1));
        nm0 = fmaxf(nm0, __shfl_xor_sync(0xffffffffu, nm0, 2));
        nm1 = fmaxf(nm1, __shfl_xor_sync(0xffffffffu, nm1, 1));
        nm1 = fmaxf(nm1, __shfl_xor_sync(0xffffffffu, nm1, 2));

        const float f0 = __expf(m0 - nm0);
        const float f1 = __expf(m1 - nm1);
        m0 = nm0; m1 = nm1;

        float rs0 = 0.f, rs1 = 0.f;
#pragma unroll
        for (int nt = 0; nt < 16; nt++) {
            sacc[nt][0] = __expf(sacc[nt][0] - nm0);
            sacc[nt][1] = __expf(sacc[nt][1] - nm0);
            sacc[nt][2] = __expf(sacc[nt][2] - nm1);
            sacc[nt][3] = __expf(sacc[nt][3] - nm1);
            rs0 += sacc[nt][0] + sacc[nt][1];
            rs1 += sacc[nt][2] + sacc[nt][3];
        }
        rs0 += __shfl_xor_sync(0xffffffffu, rs0, 1);
        rs0 += __shfl_xor_sync(0xffffffffu, rs0, 2);
        rs1 += __shfl_xor_sync(0xffffffffu, rs1, 1);
        rs1 += __shfl_xor_sync(0xffffffffu, rs1, 2);
        l0 = l0 * f0 + rs0;
        l1 = l1 * f1 + rs1;

#pragma unroll
        for (int i = 0; i < 16; i++) {
            oacc[i][0] *= f0; oacc[i][1] *= f0;
            oacc[i][2] *= f1; oacc[i][3] *= f1;
        }

        // ---- O += P @ V ----
#pragma unroll
        for (int g = 0; g < 16; g++) {
            const float u00 = __shfl_sync(0xffffffffu, sacc[g][0], src0);
            const float u01 = __shfl_sync(0xffffffffu, sacc[g][1], src0);
            const float u10 = __shfl_sync(0xffffffffu, sacc[g][0], src1);
            const float u11 = __shfl_sync(0xffffffffu, sacc[g][1], src1);
            const float u20 = __shfl_sync(0xffffffffu, sacc[g][2], src0);
            const float u21 = __shfl_sync(0xffffffffu, sacc[g][3], src0);
            const float u30 = __shfl_sync(0xffffffffu, sacc[g][2], src1);
            const float u31 = __shfl_sync(0xffffffffu, sacc[g][3], src1);
            uint32_t af[4];
            af[0] = f2tf(odd ? u01 : u00);   // P[row0][tig]
            af[1] = f2tf(odd ? u21 : u20);   // P[row1][tig]
            af[2] = f2tf(odd ? u11 : u10);   // P[row0][tig+4]
            af[3] = f2tf(odd ? u31 : u30);   // P[row1][tig+4]
            const int kb = g * 8;
#pragma unroll
            for (int ng = 0; ng < 16; ng++) {
                uint32_t bf[2] = { Vs[ng * 8 + gid][kb + tig], Vs[ng * 8 + gid][kb + tig + 4] };
                mma_tf32(oacc[ng], af, bf);
            }
        }
    }

    // ---- epilogue: O / l -> ctx ----
    const float i0 = 1.f / l0, i1 = 1.f / l1;
    float* Cb = g_ctx + b * ((long long)S * D) + h * HD;
    const long long cr0 = (long long)qt * 128 + w * 16 + gid;
#pragma unroll
    for (int ng = 0; ng < 16; ng++) {
        const int col = ng * 8 + tig * 2;
        *(float2*)(Cb + cr0 * D + col)       = make_float2(oacc[ng][0] * i0, oacc[ng][1] * i0);
        *(float2*)(Cb + (cr0 + 8) * D + col) = make_float2(oacc[ng][2] * i1, oacc[ng][3] * i1);
    }
}

// ------------------------------------------------------------------ batched weight transpose
__global__ void transpose_all_kernel(const float* __restrict__ We, const float* __restrict__ Ws,
                                     const float* __restrict__ Wq, const float* __restrict__ Wk,
                                     const float* __restrict__ Wv,
                                     float* __restrict__ wet, float* __restrict__ wst,
                                     float* __restrict__ wqkv)
{
    __shared__ float t[32][33];
    const int z = blockIdx.z;
    const float* in; float* out; int R, C;
    switch (z) {
        case 0: in = We; out = wet;              R = D;  C = D2; break;
        case 1: in = Ws; out = wst;              R = D2; C = D;  break;
        case 2: in = Wq; out = wqkv + 0 * D * D; R = D;  C = D;  break;
        case 3: in = Wk; out = wqkv + 1 * D * D; R = D;  C = D;  break;
        default: in = Wv; out = wqkv + 2 * D * D; R = D; C = D;  break;
    }
    const int bx = blockIdx.x * 32, by = blockIdx.y * 32;
    if (bx >= C || by >= R) return;
    const int tx = threadIdx.x, ty = threadIdx.y;
#pragma unroll
    for (int dy = 0; dy < 32; dy += 8)
        t[ty + dy][tx] = in[(size_t)(by + ty + dy) * C + bx + tx];
    __syncthreads();
#pragma unroll
    for (int dy = 0; dy < 32; dy += 8)
        out[(size_t)(bx + ty + dy) * R + by + tx] = t[tx][ty + dy];
}

// ------------------------------------------------------------------ LayerNorm: 1 warp per row (R10)
__global__ void __launch_bounds__(256)
ln_kernel(const float* __restrict__ x, const float* __restrict__ x2,
          const float* __restrict__ gamma, const float* __restrict__ beta,
          float* __restrict__ out)
{
    const int w = threadIdx.x >> 5, lane = threadIdx.x & 31;
    const long long row = (long long)blockIdx.x * 8 + w;
    const float* xr = x + row * D;
    const float* x2r = x2 ? x2 + row * D : nullptr;

    float4 v[4];
#pragma unroll
    for (int i = 0; i < 4; i++) {
        v[i] = *(const float4*)(xr + i * 128 + lane * 4);
        if (x2r) {
            const float4 u = *(const float4*)(x2r + i * 128 + lane * 4);
            v[i].x += u.x; v[i].y += u.y; v[i].z += u.z; v[i].w += u.w;
        }
    }

    float s = 0.f;
#pragma unroll
    for (int i = 0; i < 4; i++) s += v[i].x + v[i].y + v[i].z + v[i].w;
#pragma unroll
    for (int o = 16; o > 0; o >>= 1) s += __shfl_xor_sync(0xffffffffu, s, o);
    const float mean = s * (1.f / D);

    float q = 0.f;
#pragma unroll
    for (int i = 0; i < 4; i++) {
        v[i].x -= mean; v[i].y -= mean; v[i].z -= mean; v[i].w -= mean;
        q += v[i].x * v[i].x + v[i].y * v[i].y + v[i].z * v[i].z + v[i].w * v[i].w;
    }
#pragma unroll
    for (int o = 16; o > 0; o >>= 1) q += __shfl_xor_sync(0xffffffffu, q, o);
    const float inv = rsqrtf(q * (1.f / D) + LN_EPS);

    float* orow = out + row * D;
#pragma unroll
    for (int i = 0; i < 4; i++) {
        const float4 g = *(const float4*)(gamma + i * 128 + lane * 4);
        const float4 bt = *(const float4*)(beta + i * 128 + lane * 4);
        float4 o;
        o.x = v[i].x * inv * g.x + bt.x;
        o.y = v[i].y * inv * g.y + bt.y;
        o.z = v[i].z * inv * g.z + bt.z;
        o.w = v[i].w * inv * g.w + bt.w;
        *(float4*)(orow + i * 128 + lane * 4) = o;
    }
}

// ------------------------------------------------------------------ host
extern "C" void kernel_launch(void* const* d_in, const int* in_sizes, int n_in,
                              void* d_out, int out_size)
{
    const float* input   = (const float*)d_in[0];
    const float* pos     = (const float*)d_in[1];
    const float* We      = (const float*)d_in[2];
    const float* be      = (const float*)d_in[3];
    const float* Ws      = (const float*)d_in[4];
    const float* bs      = (const float*)d_in[5];
    const float* gamma   = (const float*)d_in[6];
    const float* beta    = (const float*)d_in[7];
    const float* Wq      = (const float*)d_in[8];
    const float* bq      = (const float*)d_in[9];
    const float* Wk      = (const float*)d_in[10];
    const float* bk      = (const float*)d_in[11];
    const float* Wv      = (const float*)d_in[12];
    const float* bv      = (const float*)d_in[13];
    const float* alpha_p = (const float*)d_in[14];
    float* out = (float*)d_out;

    float *h, *se_pre, *se, *qk, *vt, *ctx, *wet, *wst, *wqkv;
    cudaGetSymbolAddress((void**)&h,      g_h);
    cudaGetSymbolAddress((void**)&se_pre, g_se_pre);
    cudaGetSymbolAddress((void**)&se,     g_se);
    cudaGetSymbolAddress((void**)&qk,     g_qk);
    cudaGetSymbolAddress((void**)&vt,     g_vt);
    cudaGetSymbolAddress((void**)&ctx,    g_ctx);
    cudaGetSymbolAddress((void**)&wet,    g_wet);
    cudaGetSymbolAddress((void**)&wst,    g_wst);
    cudaGetSymbolAddress((void**)&wqkv,   g_wqkv);

    const int gemm_smem  = 4 * 128 * LDA * 4;                // 73728 B (double-buffered A+B)
    const int flash_smem = (3 * 128 * FLDA) * 4 + 128 * 16;  // 204800 B
    static bool attr_set = false;
    if (!attr_set) {
        cudaFuncSetAttribute(flash_kernel, cudaFuncAttributeMaxDynamicSharedMemorySize, flash_smem);
        cudaFuncSetAttribute(mma_gemm,     cudaFuncAttributeMaxDynamicSharedMemorySize, gemm_smem);
        attr_set = true;
    }

    // 0. all weight transposes in one launch
    transpose_all_kernel<<<dim3(32, 32, 5), dim3(32, 8)>>>(
        We, Ws, Wq, Wk, Wv, wet, wst, wqkv);

    // 1. h = relu(input @ We + be)
    mma_gemm<<<dim3(D2 / 128, M_TOT / 128, 1), 256, gemm_smem>>>(
        input, D, 0, 0,  wet, D, 0, 0,  h, D2, 0, 0,
        be, be, be, nullptr, nullptr, -1, 1, D, 1);
    // 2. se_pre = input + h @ Ws + bs
    mma_gemm<<<dim3(D / 128, M_TOT / 128, 1), 256, gemm_smem>>>(
        h, D2, 0, 0,  wst, D2, 0, 0,  se_pre, D, 0, 0,
        bs, bs, bs, input, nullptr, -1, 0, D2, 1);
    // 3. se = LN(se_pre)   (warp-per-row)
    ln_kernel<<<M_TOT / 8, 256>>>(se_pre, nullptr, gamma, beta, se);
    // 4. q/k/v (z=0,1,2); v written transposed into g_vt
    mma_gemm<<<dim3(D / 128, M_TOT / 128, 3), 256, gemm_smem>>>(
        se, D, 0, 0,
        wqkv, D, (long long)D * D, 0,
        qk, D, (long long)M_TOT * D, 0,
        bq, bk, bv, nullptr, vt, 2, 0, D, 1);
    // 5-7. fused flash attention -> ctx
    flash_kernel<<<dim3(S / 128, Bb * H), 256, flash_smem>>>(
        qk, qk + (size_t)M_TOT * D, pos, alpha_p);
    // 8. out = LN(se + ctx)   (warp-per-row)
    ln_kernel<<<M_TOT / 8, 256>>>(se, ctx, gamma, beta, out);
}